// round 10
// baseline (speedup 1.0000x reference)
#include <cuda_runtime.h>
#include <math.h>

// Problem shape
#define NROW   16384     // 64*256 flattened input vectors
#define NCODE  8192      // codebook entries
#define DIM    512       // embedding dim
#define NTILE  32        // NCODE / 256
#define QELEMS (NROW * DIM)          // 8388608
#define OFF_LOSS 0
#define OFF_Q    1
#define OFF_PERP (1 + QELEMS)        // 8388609
#define OFF_ENC  (2 + QELEMS)        // 8388610

#define CAP      256                 // per-row candidate capacity (u64 list)
#define EPS_F    8e-4f
#define SX       24.0f
#define SE       1040384.0f          // 127 / (1/8192)
#define TWOINV   (2.0f / (SX * SE))

// Scratch (device globals; no allocations allowed)
__device__ int g_idx[NROW];
__device__ unsigned int g_cnt[NCODE];
__device__ float g_rowsq[NROW];       // A_m = fp32(sum x^2)
__device__ float g_csq[NCODE];        // B_k = fp32(sum e^2)
__device__ double g_mse;
__device__ unsigned g_amin[NROW];     // running approx min (float bits)
__device__ unsigned g_ccnt[NROW];     // candidate counts
__device__ unsigned g_tilemin[(size_t)NROW * NTILE];   // per (row, n-tile) min bits
__device__ float g_thr[NROW];         // final threshold
__device__ unsigned long long g_cand64[(size_t)NROW * CAP];  // (dist bits, code)
__device__ unsigned g_Xq[(size_t)NROW * DIM / 4];    // s8 packed
__device__ unsigned g_Eq[(size_t)NCODE * DIM / 4];   // s8 packed

// ---------------------------------------------------------------------------
__device__ __forceinline__ unsigned smem_u32(const void* p) {
    unsigned a;
    asm("{ .reg .u64 t; cvta.to.shared.u64 t, %1; cvt.u32.u64 %0, t; }" : "=r"(a) : "l"(p));
    return a;
}
__device__ __forceinline__ void cp_async16(unsigned dst, const void* src) {
    asm volatile("cp.async.cg.shared.global [%0], [%1], 16;" :: "r"(dst), "l"(src) : "memory");
}
__device__ __forceinline__ void cp_commit() {
    asm volatile("cp.async.commit_group;" ::: "memory");
}
__device__ __forceinline__ void cp_wait1() {
    asm volatile("cp.async.wait_group 1;" ::: "memory");
}
__device__ __forceinline__ void cp_wait0() {
    asm volatile("cp.async.wait_group 0;" ::: "memory");
}
__device__ __forceinline__ void ldsm_x4(unsigned& r0, unsigned& r1, unsigned& r2, unsigned& r3,
                                        unsigned addr) {
    asm volatile("ldmatrix.sync.aligned.m8n8.x4.shared.b16 {%0,%1,%2,%3}, [%4];"
                 : "=r"(r0), "=r"(r1), "=r"(r2), "=r"(r3) : "r"(addr));
}
__device__ __forceinline__ void mma16832s8(int* c, const unsigned* a, const unsigned* b) {
    asm volatile("mma.sync.aligned.m16n8k32.row.col.s32.s8.s8.s32 "
                 "{%0,%1,%2,%3}, {%4,%5,%6,%7}, {%8,%9}, {%0,%1,%2,%3};"
                 : "+r"(c[0]), "+r"(c[1]), "+r"(c[2]), "+r"(c[3])
                 : "r"(a[0]), "r"(a[1]), "r"(a[2]), "r"(a[3]), "r"(b[0]), "r"(b[1]));
}
__device__ __forceinline__ unsigned sw128(unsigned off) { return off ^ ((off >> 3) & 0x70u); }
__device__ __forceinline__ int q8(float v, float s) {
    int q = __float2int_rn(v * s);
    return q > 127 ? 127 : (q < -127 ? -127 : q);
}

// ---------------------------------------------------------------------------
__global__ void k_init() {
    int i = blockIdx.x * blockDim.x + threadIdx.x;
    if (i < NROW) { g_amin[i] = 0x7F800000u; g_ccnt[i] = 0u; }
    if (i < NCODE) g_cnt[i] = 0u;
    if (i == 0) g_mse = 0.0;
}

// int8 quantized copies (filter precision only)
__global__ void k_convX(const float* __restrict__ X) {
    int i = blockIdx.x * blockDim.x + threadIdx.x;   // 1 float4 -> 4 bytes
    if (i >= QELEMS / 4) return;
    float4 v = ((const float4*)X)[i];
    unsigned p = (unsigned)(q8(v.x, SX) & 255) | ((unsigned)(q8(v.y, SX) & 255) << 8) |
                 ((unsigned)(q8(v.z, SX) & 255) << 16) | ((unsigned)(q8(v.w, SX) & 255) << 24);
    g_Xq[i] = p;
}
__global__ void k_convE(const float* __restrict__ E) {
    int i = blockIdx.x * blockDim.x + threadIdx.x;
    if (i >= (NCODE * DIM) / 4) return;
    float4 v = ((const float4*)E)[i];
    unsigned p = (unsigned)(q8(v.x, SE) & 255) | ((unsigned)(q8(v.y, SE) & 255) << 8) |
                 ((unsigned)(q8(v.z, SE) & 255) << 16) | ((unsigned)(q8(v.w, SE) & 255) << 24);
    g_Eq[i] = p;
}

// One warp per vector: squared L2 norms (double accum, rounded to fp32).
__global__ void k_norms(const float* __restrict__ X, const float* __restrict__ E) {
    int gwarp = (blockIdx.x * blockDim.x + threadIdx.x) >> 5;
    int lane = threadIdx.x & 31;
    const float* base; float* out; int nid;
    if (gwarp < NROW)      { base = X + (size_t)gwarp * DIM; out = g_rowsq; nid = gwarp; }
    else if (gwarp < NROW + NCODE) { nid = gwarp - NROW; base = E + (size_t)nid * DIM; out = g_csq; }
    else return;
    double s = 0.0;
    #pragma unroll 4
    for (int d = lane; d < DIM; d += 32) { float v = base[d]; s += (double)v * (double)v; }
    #pragma unroll
    for (int o = 16; o > 0; o >>= 1) s += __shfl_down_sync(0xffffffffu, s, o);
    if (lane == 0) out[nid] = (float)s;
}

// ---------------------------------------------------------------------------
// Phase 1: R6's proven int8 mma.sync GEMM filter — 512 threads, 16 warps
// (4x4), warp tile 32x64, K-tile=128 s8 (128B sw128 rows), 3-stage cp.async,
// epilogue strictly AFTER the mainloop. Per-CTA tile: 128 rows x 256 codes.
#define NKIT   4                     // 512 / 128
#define A_ST   (128 * 128)           // 16384
#define B_ST   (256 * 128)           // 32768
#define STG_BY (A_ST + B_ST)         // 49152
#define NSTG   3
#define OFF_RM (NSTG * STG_BY)       // rowmin[128] u32
#define OFF_TH (OFF_RM + 512)        // thr[128] f32
#define OFF_CS (OFF_TH + 512)        // csq_s[256] f32
#define OFF_RS (OFF_CS + 1024)       // rowsq_s[128] f32
#define GSMEM  (OFF_RS + 512)        // 150016

__global__ __launch_bounds__(512)
void k_gemm_s8() {
    extern __shared__ char sm[];
    const int tid = threadIdx.x;
    const int wid = tid >> 5, lane = tid & 31;
    const int warp_m = wid & 3, warp_n = wid >> 2;     // 4x4 warps
    const int grp = lane >> 2, tid4 = lane & 3;
    const int bm = blockIdx.y * 128, bn = blockIdx.x * 256;
    const unsigned base = smem_u32(sm);

    unsigned* rowmin = (unsigned*)(sm + OFF_RM);
    float* thr_s   = (float*)(sm + OFF_TH);
    float* csq_s   = (float*)(sm + OFF_CS);
    float* rowsq_s = (float*)(sm + OFF_RS);

    if (tid < 128) { rowmin[tid] = 0xFFFFFFFFu; rowsq_s[tid] = g_rowsq[bm + tid]; }
    if (tid < 256) csq_s[tid] = g_csq[bn + tid];

    const char* XA = (const char*)g_Xq + (size_t)bm * DIM;
    const char* EB = (const char*)g_Eq + (size_t)bn * DIM;

    int acc[2][8][4];
    #pragma unroll
    for (int mi = 0; mi < 2; mi++)
        #pragma unroll
        for (int ni = 0; ni < 8; ni++)
            #pragma unroll
            for (int c = 0; c < 4; c++) acc[mi][ni][c] = 0;

    auto issue = [&](int stage, int kt) {
        const int k0 = kt * 128;                      // byte offset in row
        const unsigned sA = base + stage * STG_BY;
        const unsigned sB = sA + A_ST;
        #pragma unroll
        for (int i = 0; i < 2; i++) {                 // A: 1024 chunks of 16B
            int u = tid + (i << 9);
            int r = u >> 3, q = u & 7;
            cp_async16(sA + sw128(r * 128 + q * 16), XA + (size_t)r * DIM + k0 + q * 16);
        }
        #pragma unroll
        for (int i = 0; i < 4; i++) {                 // B: 2048 chunks
            int u = tid + (i << 9);
            int r = u >> 3, q = u & 7;
            cp_async16(sB + sw128(r * 128 + q * 16), EB + (size_t)r * DIM + k0 + q * 16);
        }
        cp_commit();
    };

    issue(0, 0); issue(1, 1);

    // ldmatrix lane-constant row/byte offsets
    const int a_row = warp_m * 32 + (lane & 15);          // + mi*16
    const int a_kb  = (lane >> 4) * 16;
    const int b_row = warp_n * 64 + (lane & 7) + ((lane >> 4) << 3);   // + nj*16
    const int b_kb  = ((lane >> 3) & 1) * 16;

    for (int kt = 0; kt < NKIT; kt++) {
        if (kt == NKIT - 1) cp_wait0(); else cp_wait1();
        __syncthreads();
        if (kt + 2 < NKIT) issue((kt + 2) % NSTG, kt + 2);

        const unsigned sA = base + (kt % NSTG) * STG_BY;
        const unsigned sB = sA + A_ST;

        #pragma unroll
        for (int ks = 0; ks < 4; ks++) {              // 4 x k32 per 128B row
            const int kb = ks * 32;
            unsigned a[2][4], b[8][2];
            #pragma unroll
            for (int mi = 0; mi < 2; mi++)
                ldsm_x4(a[mi][0], a[mi][1], a[mi][2], a[mi][3],
                        sA + sw128((a_row + mi * 16) * 128 + kb + a_kb));
            #pragma unroll
            for (int nj = 0; nj < 4; nj++) {
                unsigned r0, r1, r2, r3;
                ldsm_x4(r0, r1, r2, r3,
                        sB + sw128((b_row + nj * 16) * 128 + kb + b_kb));
                b[nj * 2][0] = r0;     b[nj * 2][1] = r1;
                b[nj * 2 + 1][0] = r2; b[nj * 2 + 1][1] = r3;
            }
            #pragma unroll
            for (int mi = 0; mi < 2; mi++)
                #pragma unroll
                for (int ni = 0; ni < 8; ni++)
                    mma16832s8(acc[mi][ni], a[mi], b[ni]);
        }
        __syncthreads();
    }

    // --- epilogue pass 1: per-row local min of approx dist ---
    #pragma unroll
    for (int mi = 0; mi < 2; mi++) {
        const int r0 = warp_m * 32 + mi * 16 + grp;
        const float A0 = rowsq_s[r0], A1 = rowsq_s[r0 + 8];
        float m0 = 3.4e38f, m1 = 3.4e38f;
        #pragma unroll
        for (int ni = 0; ni < 8; ni++) {
            const int n = warp_n * 64 + ni * 8 + tid4 * 2;
            const float B0 = csq_s[n], B1 = csq_s[n + 1];
            const int* cc = acc[mi][ni];
            m0 = fminf(m0, fminf(A0 + B0 - TWOINV * (float)cc[0],
                                 A0 + B1 - TWOINV * (float)cc[1]));
            m1 = fminf(m1, fminf(A1 + B0 - TWOINV * (float)cc[2],
                                 A1 + B1 - TWOINV * (float)cc[3]));
        }
        atomicMin(&rowmin[r0], __float_as_uint(m0));       // dists > 0
        atomicMin(&rowmin[r0 + 8], __float_as_uint(m1));
    }
    __syncthreads();
    if (tid < 128) {
        unsigned mine = rowmin[tid];
        g_tilemin[(size_t)(bm + tid) * NTILE + blockIdx.x] = mine;   // per-tile min
        unsigned old = atomicMin(&g_amin[bm + tid], mine);
        thr_s[tid] = __uint_as_float(old < mine ? old : mine) + EPS_F;
    }
    __syncthreads();

    // --- epilogue pass 2: append (dist,code) within EPS of running min ---
    #pragma unroll
    for (int mi = 0; mi < 2; mi++) {
        const int r0 = warp_m * 32 + mi * 16 + grp;
        const float A0 = rowsq_s[r0], A1 = rowsq_s[r0 + 8];
        const float t0 = thr_s[r0], t1 = thr_s[r0 + 8];
        #pragma unroll
        for (int ni = 0; ni < 8; ni++) {
            const int n = warp_n * 64 + ni * 8 + tid4 * 2;
            const float B0 = csq_s[n], B1 = csq_s[n + 1];
            const int* cc = acc[mi][ni];
            float d00 = A0 + B0 - TWOINV * (float)cc[0];
            float d01 = A0 + B1 - TWOINV * (float)cc[1];
            float d10 = A1 + B0 - TWOINV * (float)cc[2];
            float d11 = A1 + B1 - TWOINV * (float)cc[3];
            if (d00 < t0) { unsigned p = atomicAdd(&g_ccnt[bm + r0], 1u);
                if (p < CAP) g_cand64[(size_t)(bm + r0) * CAP + p] =
                    ((unsigned long long)__float_as_uint(d00) << 32) | (unsigned)(bn + n); }
            if (d01 < t0) { unsigned p = atomicAdd(&g_ccnt[bm + r0], 1u);
                if (p < CAP) g_cand64[(size_t)(bm + r0) * CAP + p] =
                    ((unsigned long long)__float_as_uint(d01) << 32) | (unsigned)(bn + n + 1); }
            if (d10 < t1) { unsigned p = atomicAdd(&g_ccnt[bm + r0 + 8], 1u);
                if (p < CAP) g_cand64[(size_t)(bm + r0 + 8) * CAP + p] =
                    ((unsigned long long)__float_as_uint(d10) << 32) | (unsigned)(bn + n); }
            if (d11 < t1) { unsigned p = atomicAdd(&g_ccnt[bm + r0 + 8], 1u);
                if (p < CAP) g_cand64[(size_t)(bm + r0 + 8) * CAP + p] =
                    ((unsigned long long)__float_as_uint(d11) << 32) | (unsigned)(bn + n + 1); }
        }
    }
}

// ---------------------------------------------------------------------------
// Final per-row threshold from tile minima: thr = min over 32 tiles + EPS.
__global__ void k_thresh() {
    int r = blockIdx.x * blockDim.x + threadIdx.x;
    if (r >= NROW) return;
    unsigned m = 0xFFFFFFFFu;
    #pragma unroll
    for (int t = 0; t < NTILE; t++) {
        unsigned v = g_tilemin[(size_t)r * NTILE + t];
        if (v < m) m = v;
    }
    g_thr[r] = __uint_as_float(m) + EPS_F;
}

// ---------------------------------------------------------------------------
// Phase 2: filter stored candidates by the FINAL threshold, then exact
// re-verification bit-identical to R1's fp32 path (sequential ascending-k
// FMA dot; packed-key min = smallest dist then smallest index).
__global__ void k_select(const float* __restrict__ X, const float* __restrict__ E) {
    int gid = blockIdx.x * blockDim.x + threadIdx.x;
    int r = gid >> 3, slot = gid & 7;
    if (r >= NROW) return;
    unsigned cnt = g_ccnt[r];
    const float thr = g_thr[r];
    const float* x = X + (size_t)r * DIM;
    const float A = g_rowsq[r];
    unsigned long long best = 0xFFFFFFFFFFFFFFFFULL;
    if (cnt <= CAP) {
        for (unsigned i = slot; i < cnt; i += 8) {
            unsigned long long kc = g_cand64[(size_t)r * CAP + i];
            if (__uint_as_float((unsigned)(kc >> 32)) >= thr) continue;
            int c = (int)(kc & 0xFFFFu);
            const float* e = E + (size_t)c * DIM;
            float acc = 0.0f;
            #pragma unroll 8
            for (int k = 0; k < DIM; k++) acc = fmaf(x[k], e[k], acc);
            float dist = __fsub_rn(__fadd_rn(A, g_csq[c]), 2.0f * acc);
            unsigned long long key =
                ((unsigned long long)__float_as_uint(dist) << 32) | (unsigned)c;
            if (key < best) best = key;
        }
    } else {
        // overflow fallback (expected ~never): scan tiles whose min < thr
        for (int t = 0; t < NTILE; t++) {
            if (__uint_as_float(g_tilemin[(size_t)r * NTILE + t]) >= thr) continue;
            for (int c = t * 256 + slot; c < (t + 1) * 256; c += 8) {
                const float* e = E + (size_t)c * DIM;
                float acc = 0.0f;
                #pragma unroll 8
                for (int k = 0; k < DIM; k++) acc = fmaf(x[k], e[k], acc);
                float dist = __fsub_rn(__fadd_rn(A, g_csq[c]), 2.0f * acc);
                unsigned long long key =
                    ((unsigned long long)__float_as_uint(dist) << 32) | (unsigned)c;
                if (key < best) best = key;
            }
        }
    }
    #pragma unroll
    for (int o = 4; o > 0; o >>= 1) {
        unsigned long long t = __shfl_down_sync(0xffffffffu, best, o, 8);
        if (t < best) best = t;
    }
    if (slot == 0) {
        int idx = (int)(unsigned)(best & 0xFFFFFFFFu);
        g_idx[r] = idx;
        atomicAdd(&g_cnt[idx], 1u);
    }
}

// ---------------------------------------------------------------------------
__global__ void k_quant_loss(const float* __restrict__ X, const float* __restrict__ E,
                             float* __restrict__ q_out) {
    __shared__ double sred[8];
    int i = blockIdx.x * blockDim.x + threadIdx.x;
    int row = i >> 9;
    int d = i & 511;
    int idx = g_idx[row];
    float q = E[(size_t)idx * DIM + d];
    float x = X[i];
    float diff = __fsub_rn(q, x);
    q_out[i] = __fadd_rn(x, diff);
    double local = (double)diff * (double)diff;
    #pragma unroll
    for (int o = 16; o > 0; o >>= 1) local += __shfl_down_sync(0xffffffffu, local, o);
    int lane = threadIdx.x & 31, w = threadIdx.x >> 5;
    if (lane == 0) sred[w] = local;
    __syncthreads();
    if (w == 0) {
        double v = (lane < 8) ? sred[lane] : 0.0;
        #pragma unroll
        for (int o = 4; o > 0; o >>= 1) v += __shfl_down_sync(0xffffffffu, v, o);
        if (lane == 0) atomicAdd(&g_mse, v);
    }
}

// Zero encodings: misaligned head/tail scalars + float4 body (streaming).
__global__ void k_zero_enc(float* __restrict__ p) {
    const size_t n4 = 33554431;                    // (NROW*NCODE - 4) / 4
    float4* p4 = (float4*)(p + 2);
    size_t stride = (size_t)gridDim.x * blockDim.x;
    float4 z = make_float4(0.f, 0.f, 0.f, 0.f);
    for (size_t i = blockIdx.x * (size_t)blockDim.x + threadIdx.x; i < n4; i += stride)
        __stcs(&p4[i], z);
    if (blockIdx.x == 0 && threadIdx.x == 0) {
        p[0] = 0.f; p[1] = 0.f;
        p[(size_t)NROW * NCODE - 2] = 0.f; p[(size_t)NROW * NCODE - 1] = 0.f;
    }
}

__global__ void k_ones(float* __restrict__ enc) {
    int i = blockIdx.x * blockDim.x + threadIdx.x;
    if (i < NROW) enc[(size_t)i * NCODE + g_idx[i]] = 1.0f;
}

__global__ void k_final(float* __restrict__ out) {
    __shared__ double sred[8];
    int t = threadIdx.x;
    double h = 0.0;
    for (int k = t; k < NCODE; k += 256) {
        float p = (float)g_cnt[k] * (1.0f / 16384.0f);
        float arg = __fadd_rn(p, 1e-10f);
        h += (double)p * log((double)arg);
    }
    #pragma unroll
    for (int o = 16; o > 0; o >>= 1) h += __shfl_down_sync(0xffffffffu, h, o);
    int lane = t & 31, w = t >> 5;
    if (lane == 0) sred[w] = h;
    __syncthreads();
    if (w == 0) {
        double v = (lane < 8) ? sred[lane] : 0.0;
        #pragma unroll
        for (int o = 4; o > 0; o >>= 1) v += __shfl_down_sync(0xffffffffu, v, o);
        if (lane == 0) {
            out[OFF_PERP] = (float)exp(-v);
            float m = (float)(g_mse / (double)QELEMS);
            out[OFF_LOSS] = __fadd_rn(m, 0.25f * m);
        }
    }
}

// ---------------------------------------------------------------------------
extern "C" void kernel_launch(void* const* d_in, const int* in_sizes, int n_in,
                              void* d_out, int out_size) {
    const float* X = (const float*)d_in[0];   // [64,256,512] fp32
    const float* E = (const float*)d_in[1];   // [8192,512] fp32
    float* out = (float*)d_out;

    static int inited = 0;
    static cudaStream_t s1;
    static cudaEvent_t ev_fork, ev_join;
    if (!inited) {
        cudaFuncSetAttribute(k_gemm_s8, cudaFuncAttributeMaxDynamicSharedMemorySize, GSMEM);
        cudaStreamCreateWithFlags(&s1, cudaStreamNonBlocking);
        cudaEventCreateWithFlags(&ev_fork, cudaEventDisableTiming);
        cudaEventCreateWithFlags(&ev_join, cudaEventDisableTiming);
        inited = 1;
    }

    // Fork: the 536MB encodings zero-fill is independent of everything up to
    // k_ones — run it concurrently with the conv/norms/GEMM/select phase.
    cudaEventRecord(ev_fork, 0);
    cudaStreamWaitEvent(s1, ev_fork, 0);
    k_zero_enc<<<8192, 256, 0, s1>>>(out + OFF_ENC);
    cudaEventRecord(ev_join, s1);

    k_init<<<64, 256>>>();
    k_convX<<<(QELEMS / 4) / 256, 256>>>(X);
    k_convE<<<((NCODE * DIM) / 4) / 256, 256>>>(E);
    k_norms<<<3072, 256>>>(X, E);

    dim3 grid(NCODE / 256, NROW / 128);        // (32, 128)
    k_gemm_s8<<<grid, 512, GSMEM>>>();

    k_thresh<<<64, 256>>>();
    k_select<<<(NROW * 8) / 256, 256>>>(X, E);
    k_quant_loss<<<QELEMS / 256, 256>>>(X, E, out + OFF_Q);

    // Join: ones must land after the zero-fill completes.
    cudaStreamWaitEvent(0, ev_join, 0);
    k_ones<<<64, 256>>>(out + OFF_ENC);
    k_final<<<1, 256>>>(out);
}

// round 11
// speedup vs baseline: 1.0069x; 1.0069x over previous
#include <cuda_runtime.h>
#include <math.h>

// Problem shape
#define NROW   16384     // 64*256 flattened input vectors
#define NCODE  8192      // codebook entries
#define DIM    512       // embedding dim
#define NTILE  32        // NCODE / 256
#define QELEMS (NROW * DIM)          // 8388608
#define OFF_LOSS 0
#define OFF_Q    1
#define OFF_PERP (1 + QELEMS)        // 8388609
#define OFF_ENC  (2 + QELEMS)        // 8388610

#define CAP      256                 // per-row candidate capacity (u64 list)
#define EPS_F    8e-4f
#define SX       24.0f
#define SE       1040384.0f          // 127 / (1/8192)
#define TWOINV   (2.0f / (SX * SE))

// Scratch (device globals; no allocations allowed)
__device__ int g_idx[NROW];
__device__ unsigned int g_cnt[NCODE];
__device__ float g_rowsq[NROW];       // A_m = fp32(sum x^2)
__device__ float g_csq[NCODE];        // B_k = fp32(sum e^2)
__device__ double g_mse;
__device__ unsigned g_amin[NROW];     // running approx min (float bits)
__device__ unsigned g_ccnt[NROW];     // candidate counts
__device__ unsigned g_tilemin[(size_t)NROW * NTILE];   // per (row, n-tile) min bits
__device__ float g_thr[NROW];         // final threshold
__device__ unsigned long long g_cand64[(size_t)NROW * CAP];  // (dist bits, code)
__device__ unsigned g_Xq[(size_t)NROW * DIM / 4];    // s8 packed
__device__ unsigned g_Eq[(size_t)NCODE * DIM / 4];   // s8 packed

// ---------------------------------------------------------------------------
__device__ __forceinline__ unsigned smem_u32(const void* p) {
    unsigned a;
    asm("{ .reg .u64 t; cvta.to.shared.u64 t, %1; cvt.u32.u64 %0, t; }" : "=r"(a) : "l"(p));
    return a;
}
__device__ __forceinline__ void cp_async16(unsigned dst, const void* src) {
    asm volatile("cp.async.cg.shared.global [%0], [%1], 16;" :: "r"(dst), "l"(src) : "memory");
}
__device__ __forceinline__ void cp_commit() {
    asm volatile("cp.async.commit_group;" ::: "memory");
}
__device__ __forceinline__ void cp_wait1() {
    asm volatile("cp.async.wait_group 1;" ::: "memory");
}
__device__ __forceinline__ void cp_wait0() {
    asm volatile("cp.async.wait_group 0;" ::: "memory");
}
__device__ __forceinline__ void ldsm_x4(unsigned& r0, unsigned& r1, unsigned& r2, unsigned& r3,
                                        unsigned addr) {
    asm volatile("ldmatrix.sync.aligned.m8n8.x4.shared.b16 {%0,%1,%2,%3}, [%4];"
                 : "=r"(r0), "=r"(r1), "=r"(r2), "=r"(r3) : "r"(addr));
}
__device__ __forceinline__ void mma16832s8(int* c, const unsigned* a, const unsigned* b) {
    asm volatile("mma.sync.aligned.m16n8k32.row.col.s32.s8.s8.s32 "
                 "{%0,%1,%2,%3}, {%4,%5,%6,%7}, {%8,%9}, {%0,%1,%2,%3};"
                 : "+r"(c[0]), "+r"(c[1]), "+r"(c[2]), "+r"(c[3])
                 : "r"(a[0]), "r"(a[1]), "r"(a[2]), "r"(a[3]), "r"(b[0]), "r"(b[1]));
}
__device__ __forceinline__ unsigned sw128(unsigned off) { return off ^ ((off >> 3) & 0x70u); }
__device__ __forceinline__ int q8(float v, float s) {
    int q = __float2int_rn(v * s);
    return q > 127 ? 127 : (q < -127 ? -127 : q);
}

// ---------------------------------------------------------------------------
__global__ void k_init() {
    int i = blockIdx.x * blockDim.x + threadIdx.x;
    if (i < NROW) { g_amin[i] = 0x7F800000u; g_ccnt[i] = 0u; }
    if (i < NCODE) g_cnt[i] = 0u;
    if (i == 0) g_mse = 0.0;
}

// int8 quantized copies (filter precision only)
__global__ void k_convX(const float* __restrict__ X) {
    int i = blockIdx.x * blockDim.x + threadIdx.x;   // 1 float4 -> 4 bytes
    if (i >= QELEMS / 4) return;
    float4 v = ((const float4*)X)[i];
    unsigned p = (unsigned)(q8(v.x, SX) & 255) | ((unsigned)(q8(v.y, SX) & 255) << 8) |
                 ((unsigned)(q8(v.z, SX) & 255) << 16) | ((unsigned)(q8(v.w, SX) & 255) << 24);
    g_Xq[i] = p;
}
__global__ void k_convE(const float* __restrict__ E) {
    int i = blockIdx.x * blockDim.x + threadIdx.x;
    if (i >= (NCODE * DIM) / 4) return;
    float4 v = ((const float4*)E)[i];
    unsigned p = (unsigned)(q8(v.x, SE) & 255) | ((unsigned)(q8(v.y, SE) & 255) << 8) |
                 ((unsigned)(q8(v.z, SE) & 255) << 16) | ((unsigned)(q8(v.w, SE) & 255) << 24);
    g_Eq[i] = p;
}

// One warp per vector: squared L2 norms (double accum, rounded to fp32).
__global__ void k_norms(const float* __restrict__ X, const float* __restrict__ E) {
    int gwarp = (blockIdx.x * blockDim.x + threadIdx.x) >> 5;
    int lane = threadIdx.x & 31;
    const float* base; float* out; int nid;
    if (gwarp < NROW)      { base = X + (size_t)gwarp * DIM; out = g_rowsq; nid = gwarp; }
    else if (gwarp < NROW + NCODE) { nid = gwarp - NROW; base = E + (size_t)nid * DIM; out = g_csq; }
    else return;
    double s = 0.0;
    #pragma unroll 4
    for (int d = lane; d < DIM; d += 32) { float v = base[d]; s += (double)v * (double)v; }
    #pragma unroll
    for (int o = 16; o > 0; o >>= 1) s += __shfl_down_sync(0xffffffffu, s, o);
    if (lane == 0) out[nid] = (float)s;
}

// ---------------------------------------------------------------------------
// Phase 1: R6's proven int8 mma.sync GEMM filter — 512 threads, 16 warps
// (4x4), warp tile 32x64, K-tile=128 s8 (128B sw128 rows), 3-stage cp.async,
// epilogue strictly AFTER the mainloop. Per-CTA tile: 128 rows x 256 codes.
// Grid mapping: x = row-tile (fast), y = code-tile -> consecutive CTAs share
// the 128KB B panel in L2 (halves L2 read traffic vs sharing the 64KB A).
#define NKIT   4                     // 512 / 128
#define A_ST   (128 * 128)           // 16384
#define B_ST   (256 * 128)           // 32768
#define STG_BY (A_ST + B_ST)         // 49152
#define NSTG   3
#define OFF_RM (NSTG * STG_BY)       // rowmin[128] u32
#define OFF_TH (OFF_RM + 512)        // thr[128] f32
#define OFF_CS (OFF_TH + 512)        // csq_s[256] f32
#define OFF_RS (OFF_CS + 1024)       // rowsq_s[128] f32
#define GSMEM  (OFF_RS + 512)        // 150016

__global__ __launch_bounds__(512)
void k_gemm_s8() {
    extern __shared__ char sm[];
    const int tid = threadIdx.x;
    const int wid = tid >> 5, lane = tid & 31;
    const int warp_m = wid & 3, warp_n = wid >> 2;     // 4x4 warps
    const int grp = lane >> 2, tid4 = lane & 3;
    const int bm = blockIdx.x * 128, bn = blockIdx.y * 256;   // x = row tile
    const unsigned base = smem_u32(sm);

    unsigned* rowmin = (unsigned*)(sm + OFF_RM);
    float* thr_s   = (float*)(sm + OFF_TH);
    float* csq_s   = (float*)(sm + OFF_CS);
    float* rowsq_s = (float*)(sm + OFF_RS);

    if (tid < 128) { rowmin[tid] = 0xFFFFFFFFu; rowsq_s[tid] = g_rowsq[bm + tid]; }
    if (tid < 256) csq_s[tid] = g_csq[bn + tid];

    const char* XA = (const char*)g_Xq + (size_t)bm * DIM;
    const char* EB = (const char*)g_Eq + (size_t)bn * DIM;

    int acc[2][8][4];
    #pragma unroll
    for (int mi = 0; mi < 2; mi++)
        #pragma unroll
        for (int ni = 0; ni < 8; ni++)
            #pragma unroll
            for (int c = 0; c < 4; c++) acc[mi][ni][c] = 0;

    auto issue = [&](int stage, int kt) {
        const int k0 = kt * 128;                      // byte offset in row
        const unsigned sA = base + stage * STG_BY;
        const unsigned sB = sA + A_ST;
        #pragma unroll
        for (int i = 0; i < 2; i++) {                 // A: 1024 chunks of 16B
            int u = tid + (i << 9);
            int r = u >> 3, q = u & 7;
            cp_async16(sA + sw128(r * 128 + q * 16), XA + (size_t)r * DIM + k0 + q * 16);
        }
        #pragma unroll
        for (int i = 0; i < 4; i++) {                 // B: 2048 chunks
            int u = tid + (i << 9);
            int r = u >> 3, q = u & 7;
            cp_async16(sB + sw128(r * 128 + q * 16), EB + (size_t)r * DIM + k0 + q * 16);
        }
        cp_commit();
    };

    issue(0, 0); issue(1, 1);

    // ldmatrix lane-constant row/byte offsets
    const int a_row = warp_m * 32 + (lane & 15);          // + mi*16
    const int a_kb  = (lane >> 4) * 16;
    const int b_row = warp_n * 64 + (lane & 7) + ((lane >> 4) << 3);   // + nj*16
    const int b_kb  = ((lane >> 3) & 1) * 16;

    for (int kt = 0; kt < NKIT; kt++) {
        if (kt == NKIT - 1) cp_wait0(); else cp_wait1();
        __syncthreads();
        if (kt + 2 < NKIT) issue((kt + 2) % NSTG, kt + 2);

        const unsigned sA = base + (kt % NSTG) * STG_BY;
        const unsigned sB = sA + A_ST;

        #pragma unroll
        for (int ks = 0; ks < 4; ks++) {              // 4 x k32 per 128B row
            const int kb = ks * 32;
            unsigned a[2][4], b[8][2];
            #pragma unroll
            for (int mi = 0; mi < 2; mi++)
                ldsm_x4(a[mi][0], a[mi][1], a[mi][2], a[mi][3],
                        sA + sw128((a_row + mi * 16) * 128 + kb + a_kb));
            #pragma unroll
            for (int nj = 0; nj < 4; nj++) {
                unsigned r0, r1, r2, r3;
                ldsm_x4(r0, r1, r2, r3,
                        sB + sw128((b_row + nj * 16) * 128 + kb + b_kb));
                b[nj * 2][0] = r0;     b[nj * 2][1] = r1;
                b[nj * 2 + 1][0] = r2; b[nj * 2 + 1][1] = r3;
            }
            #pragma unroll
            for (int mi = 0; mi < 2; mi++)
                #pragma unroll
                for (int ni = 0; ni < 8; ni++)
                    mma16832s8(acc[mi][ni], a[mi], b[ni]);
        }
        __syncthreads();
    }

    // --- epilogue pass 1: per-row local min of approx dist ---
    #pragma unroll
    for (int mi = 0; mi < 2; mi++) {
        const int r0 = warp_m * 32 + mi * 16 + grp;
        const float A0 = rowsq_s[r0], A1 = rowsq_s[r0 + 8];
        float m0 = 3.4e38f, m1 = 3.4e38f;
        #pragma unroll
        for (int ni = 0; ni < 8; ni++) {
            const int n = warp_n * 64 + ni * 8 + tid4 * 2;
            const float B0 = csq_s[n], B1 = csq_s[n + 1];
            const int* cc = acc[mi][ni];
            m0 = fminf(m0, fminf(A0 + B0 - TWOINV * (float)cc[0],
                                 A0 + B1 - TWOINV * (float)cc[1]));
            m1 = fminf(m1, fminf(A1 + B0 - TWOINV * (float)cc[2],
                                 A1 + B1 - TWOINV * (float)cc[3]));
        }
        atomicMin(&rowmin[r0], __float_as_uint(m0));       // dists > 0
        atomicMin(&rowmin[r0 + 8], __float_as_uint(m1));
    }
    __syncthreads();
    if (tid < 128) {
        unsigned mine = rowmin[tid];
        g_tilemin[(size_t)(bm + tid) * NTILE + blockIdx.y] = mine;   // per-tile min
        unsigned old = atomicMin(&g_amin[bm + tid], mine);
        thr_s[tid] = __uint_as_float(old < mine ? old : mine) + EPS_F;
    }
    __syncthreads();

    // --- epilogue pass 2: append (dist,code) within EPS of running min ---
    #pragma unroll
    for (int mi = 0; mi < 2; mi++) {
        const int r0 = warp_m * 32 + mi * 16 + grp;
        const float A0 = rowsq_s[r0], A1 = rowsq_s[r0 + 8];
        const float t0 = thr_s[r0], t1 = thr_s[r0 + 8];
        #pragma unroll
        for (int ni = 0; ni < 8; ni++) {
            const int n = warp_n * 64 + ni * 8 + tid4 * 2;
            const float B0 = csq_s[n], B1 = csq_s[n + 1];
            const int* cc = acc[mi][ni];
            float d00 = A0 + B0 - TWOINV * (float)cc[0];
            float d01 = A0 + B1 - TWOINV * (float)cc[1];
            float d10 = A1 + B0 - TWOINV * (float)cc[2];
            float d11 = A1 + B1 - TWOINV * (float)cc[3];
            if (d00 < t0) { unsigned p = atomicAdd(&g_ccnt[bm + r0], 1u);
                if (p < CAP) g_cand64[(size_t)(bm + r0) * CAP + p] =
                    ((unsigned long long)__float_as_uint(d00) << 32) | (unsigned)(bn + n); }
            if (d01 < t0) { unsigned p = atomicAdd(&g_ccnt[bm + r0], 1u);
                if (p < CAP) g_cand64[(size_t)(bm + r0) * CAP + p] =
                    ((unsigned long long)__float_as_uint(d01) << 32) | (unsigned)(bn + n + 1); }
            if (d10 < t1) { unsigned p = atomicAdd(&g_ccnt[bm + r0 + 8], 1u);
                if (p < CAP) g_cand64[(size_t)(bm + r0 + 8) * CAP + p] =
                    ((unsigned long long)__float_as_uint(d10) << 32) | (unsigned)(bn + n); }
            if (d11 < t1) { unsigned p = atomicAdd(&g_ccnt[bm + r0 + 8], 1u);
                if (p < CAP) g_cand64[(size_t)(bm + r0 + 8) * CAP + p] =
                    ((unsigned long long)__float_as_uint(d11) << 32) | (unsigned)(bn + n + 1); }
        }
    }
}

// ---------------------------------------------------------------------------
// Final per-row threshold from tile minima: thr = min over 32 tiles + EPS.
__global__ void k_thresh() {
    int r = blockIdx.x * blockDim.x + threadIdx.x;
    if (r >= NROW) return;
    unsigned m = 0xFFFFFFFFu;
    #pragma unroll
    for (int t = 0; t < NTILE; t++) {
        unsigned v = g_tilemin[(size_t)r * NTILE + t];
        if (v < m) m = v;
    }
    g_thr[r] = __uint_as_float(m) + EPS_F;
}

// ---------------------------------------------------------------------------
// Phase 2: filter stored candidates by the FINAL threshold, then exact
// re-verification bit-identical to R1's fp32 path (sequential ascending-k
// FMA dot; packed-key min = smallest dist then smallest index).
__global__ void k_select(const float* __restrict__ X, const float* __restrict__ E) {
    int gid = blockIdx.x * blockDim.x + threadIdx.x;
    int r = gid >> 3, slot = gid & 7;
    if (r >= NROW) return;
    unsigned cnt = g_ccnt[r];
    const float thr = g_thr[r];
    const float* x = X + (size_t)r * DIM;
    const float A = g_rowsq[r];
    unsigned long long best = 0xFFFFFFFFFFFFFFFFULL;
    if (cnt <= CAP) {
        for (unsigned i = slot; i < cnt; i += 8) {
            unsigned long long kc = g_cand64[(size_t)r * CAP + i];
            if (__uint_as_float((unsigned)(kc >> 32)) >= thr) continue;
            int c = (int)(kc & 0xFFFFu);
            const float* e = E + (size_t)c * DIM;
            float acc = 0.0f;
            #pragma unroll 8
            for (int k = 0; k < DIM; k++) acc = fmaf(x[k], e[k], acc);
            float dist = __fsub_rn(__fadd_rn(A, g_csq[c]), 2.0f * acc);
            unsigned long long key =
                ((unsigned long long)__float_as_uint(dist) << 32) | (unsigned)c;
            if (key < best) best = key;
        }
    } else {
        // overflow fallback (expected ~never): scan tiles whose min < thr
        for (int t = 0; t < NTILE; t++) {
            if (__uint_as_float(g_tilemin[(size_t)r * NTILE + t]) >= thr) continue;
            for (int c = t * 256 + slot; c < (t + 1) * 256; c += 8) {
                const float* e = E + (size_t)c * DIM;
                float acc = 0.0f;
                #pragma unroll 8
                for (int k = 0; k < DIM; k++) acc = fmaf(x[k], e[k], acc);
                float dist = __fsub_rn(__fadd_rn(A, g_csq[c]), 2.0f * acc);
                unsigned long long key =
                    ((unsigned long long)__float_as_uint(dist) << 32) | (unsigned)c;
                if (key < best) best = key;
            }
        }
    }
    #pragma unroll
    for (int o = 4; o > 0; o >>= 1) {
        unsigned long long t = __shfl_down_sync(0xffffffffu, best, o, 8);
        if (t < best) best = t;
    }
    if (slot == 0) {
        int idx = (int)(unsigned)(best & 0xFFFFFFFFu);
        g_idx[r] = idx;
        atomicAdd(&g_cnt[idx], 1u);
    }
}

// ---------------------------------------------------------------------------
__global__ void k_quant_loss(const float* __restrict__ X, const float* __restrict__ E,
                             float* __restrict__ q_out) {
    __shared__ double sred[8];
    int i = blockIdx.x * blockDim.x + threadIdx.x;
    int row = i >> 9;
    int d = i & 511;
    int idx = g_idx[row];
    float q = E[(size_t)idx * DIM + d];
    float x = X[i];
    float diff = __fsub_rn(q, x);
    q_out[i] = __fadd_rn(x, diff);
    double local = (double)diff * (double)diff;
    #pragma unroll
    for (int o = 16; o > 0; o >>= 1) local += __shfl_down_sync(0xffffffffu, local, o);
    int lane = threadIdx.x & 31, w = threadIdx.x >> 5;
    if (lane == 0) sred[w] = local;
    __syncthreads();
    if (w == 0) {
        double v = (lane < 8) ? sred[lane] : 0.0;
        #pragma unroll
        for (int o = 4; o > 0; o >>= 1) v += __shfl_down_sync(0xffffffffu, v, o);
        if (lane == 0) atomicAdd(&g_mse, v);
    }
}

// Zero encodings: small co-resident grid (shares SMs with the GEMM), grid-
// stride streaming stores; head/tail scalars for the misaligned base.
__global__ void k_zero_enc(float* __restrict__ p) {
    const size_t n4 = 33554431;                    // (NROW*NCODE - 4) / 4
    float4* p4 = (float4*)(p + 2);
    size_t stride = (size_t)gridDim.x * blockDim.x;
    float4 z = make_float4(0.f, 0.f, 0.f, 0.f);
    for (size_t i = blockIdx.x * (size_t)blockDim.x + threadIdx.x; i < n4; i += stride)
        __stcs(&p4[i], z);
    if (blockIdx.x == 0 && threadIdx.x == 0) {
        p[0] = 0.f; p[1] = 0.f;
        p[(size_t)NROW * NCODE - 2] = 0.f; p[(size_t)NROW * NCODE - 1] = 0.f;
    }
}

__global__ void k_ones(float* __restrict__ enc) {
    int i = blockIdx.x * blockDim.x + threadIdx.x;
    if (i < NROW) enc[(size_t)i * NCODE + g_idx[i]] = 1.0f;
}

__global__ void k_final(float* __restrict__ out) {
    __shared__ double sred[8];
    int t = threadIdx.x;
    double h = 0.0;
    for (int k = t; k < NCODE; k += 256) {
        float p = (float)g_cnt[k] * (1.0f / 16384.0f);
        float arg = __fadd_rn(p, 1e-10f);
        h += (double)p * log((double)arg);
    }
    #pragma unroll
    for (int o = 16; o > 0; o >>= 1) h += __shfl_down_sync(0xffffffffu, h, o);
    int lane = t & 31, w = t >> 5;
    if (lane == 0) sred[w] = h;
    __syncthreads();
    if (w == 0) {
        double v = (lane < 8) ? sred[lane] : 0.0;
        #pragma unroll
        for (int o = 4; o > 0; o >>= 1) v += __shfl_down_sync(0xffffffffu, v, o);
        if (lane == 0) {
            out[OFF_PERP] = (float)exp(-v);
            float m = (float)(g_mse / (double)QELEMS);
            out[OFF_LOSS] = __fadd_rn(m, 0.25f * m);
        }
    }
}

// ---------------------------------------------------------------------------
extern "C" void kernel_launch(void* const* d_in, const int* in_sizes, int n_in,
                              void* d_out, int out_size) {
    const float* X = (const float*)d_in[0];   // [64,256,512] fp32
    const float* E = (const float*)d_in[1];   // [8192,512] fp32
    float* out = (float*)d_out;

    static int inited = 0;
    static cudaStream_t s1;
    static cudaEvent_t ev_fork, ev_join;
    if (!inited) {
        cudaFuncSetAttribute(k_gemm_s8, cudaFuncAttributeMaxDynamicSharedMemorySize, GSMEM);
        cudaStreamCreateWithFlags(&s1, cudaStreamNonBlocking);
        cudaEventCreateWithFlags(&ev_fork, cudaEventDisableTiming);
        cudaEventCreateWithFlags(&ev_join, cudaEventDisableTiming);
        inited = 1;
    }

    // Fork: 536MB encodings zero-fill as a SMALL co-resident grid so it
    // shares SMs with the GEMM instead of serializing ahead of it.
    cudaEventRecord(ev_fork, 0);
    cudaStreamWaitEvent(s1, ev_fork, 0);
    k_zero_enc<<<296, 256, 0, s1>>>(out + OFF_ENC);
    cudaEventRecord(ev_join, s1);

    k_init<<<64, 256>>>();
    k_convX<<<(QELEMS / 4) / 256, 256>>>(X);
    k_convE<<<((NCODE * DIM) / 4) / 256, 256>>>(E);
    k_norms<<<3072, 256>>>(X, E);

    dim3 grid(NROW / 128, NCODE / 256);        // x = row tile (fast), y = code tile
    k_gemm_s8<<<grid, 512, GSMEM>>>();

    k_thresh<<<64, 256>>>();
    k_select<<<(NROW * 8) / 256, 256>>>(X, E);
    k_quant_loss<<<QELEMS / 256, 256>>>(X, E, out + OFF_Q);

    // Join: ones must land after the zero-fill completes.
    cudaStreamWaitEvent(0, ev_join, 0);
    k_ones<<<64, 256>>>(out + OFF_ENC);
    k_final<<<1, 256>>>(out);
}

// round 13
// speedup vs baseline: 1.0676x; 1.0602x over previous
#include <cuda_runtime.h>
#include <math.h>

// Problem shape
#define NROW   16384     // 64*256 flattened input vectors
#define NCODE  8192      // codebook entries
#define DIM    512       // embedding dim
#define NTILE  64        // NCODE / 128
#define QELEMS (NROW * DIM)          // 8388608
#define OFF_LOSS 0
#define OFF_Q    1
#define OFF_PERP (1 + QELEMS)        // 8388609
#define OFF_ENC  (2 + QELEMS)        // 8388610

#define CAP      256                 // per-row candidate capacity (u64 list)
#define EPS_F    8e-4f
#define SX       24.0f
#define SE       1040384.0f          // 127 / (1/8192)
#define TWOINV   (2.0f / (SX * SE))

// Scratch (device globals; no allocations allowed)
__device__ int g_idx[NROW];
__device__ unsigned int g_cnt[NCODE];
__device__ float g_rowsq[NROW];       // A_m = fp32(sum x^2)
__device__ float g_csq[NCODE];        // B_k = fp32(sum e^2)
__device__ double g_mse;
__device__ unsigned g_amin[NROW];     // running approx min (float bits)
__device__ unsigned g_ccnt[NROW];     // candidate counts
__device__ unsigned g_tilemin[(size_t)NROW * NTILE];   // per (row, n-tile) min bits
__device__ float g_thr[NROW];         // final threshold
__device__ unsigned long long g_cand64[(size_t)NROW * CAP];  // (dist bits, code)
__device__ unsigned g_Xq[(size_t)NROW * DIM / 4];    // s8 packed
__device__ unsigned g_Eq[(size_t)NCODE * DIM / 4];   // s8 packed

// ---------------------------------------------------------------------------
__device__ __forceinline__ unsigned smem_u32(const void* p) {
    unsigned a;
    asm("{ .reg .u64 t; cvta.to.shared.u64 t, %1; cvt.u32.u64 %0, t; }" : "=r"(a) : "l"(p));
    return a;
}
__device__ __forceinline__ void cp_async16(unsigned dst, const void* src) {
    asm volatile("cp.async.cg.shared.global [%0], [%1], 16;" :: "r"(dst), "l"(src) : "memory");
}
__device__ __forceinline__ void cp_commit() {
    asm volatile("cp.async.commit_group;" ::: "memory");
}
__device__ __forceinline__ void cp_wait1() {
    asm volatile("cp.async.wait_group 1;" ::: "memory");
}
__device__ __forceinline__ void cp_wait0() {
    asm volatile("cp.async.wait_group 0;" ::: "memory");
}
__device__ __forceinline__ void ldsm_x4(unsigned& r0, unsigned& r1, unsigned& r2, unsigned& r3,
                                        unsigned addr) {
    asm volatile("ldmatrix.sync.aligned.m8n8.x4.shared.b16 {%0,%1,%2,%3}, [%4];"
                 : "=r"(r0), "=r"(r1), "=r"(r2), "=r"(r3) : "r"(addr));
}
__device__ __forceinline__ void mma16832s8(int* c, const unsigned* a, const unsigned* b) {
    asm volatile("mma.sync.aligned.m16n8k32.row.col.s32.s8.s8.s32 "
                 "{%0,%1,%2,%3}, {%4,%5,%6,%7}, {%8,%9}, {%0,%1,%2,%3};"
                 : "+r"(c[0]), "+r"(c[1]), "+r"(c[2]), "+r"(c[3])
                 : "r"(a[0]), "r"(a[1]), "r"(a[2]), "r"(a[3]), "r"(b[0]), "r"(b[1]));
}
__device__ __forceinline__ unsigned sw128(unsigned off) { return off ^ ((off >> 3) & 0x70u); }
__device__ __forceinline__ int q8(float v, float s) {
    int q = __float2int_rn(v * s);
    return q > 127 ? 127 : (q < -127 ? -127 : q);
}

// ---------------------------------------------------------------------------
// Fused int8 quantization of X and E (filter precision only).
__global__ void k_conv(const float* __restrict__ X, const float* __restrict__ E) {
    int i = blockIdx.x * blockDim.x + threadIdx.x;
    if (i < QELEMS / 4) {
        float4 v = ((const float4*)X)[i];
        g_Xq[i] = (unsigned)(q8(v.x, SX) & 255) | ((unsigned)(q8(v.y, SX) & 255) << 8) |
                  ((unsigned)(q8(v.z, SX) & 255) << 16) | ((unsigned)(q8(v.w, SX) & 255) << 24);
    } else {
        int j = i - QELEMS / 4;
        if (j >= (NCODE * DIM) / 4) return;
        float4 v = ((const float4*)E)[j];
        g_Eq[j] = (unsigned)(q8(v.x, SE) & 255) | ((unsigned)(q8(v.y, SE) & 255) << 8) |
                  ((unsigned)(q8(v.z, SE) & 255) << 16) | ((unsigned)(q8(v.w, SE) & 255) << 24);
    }
}

__global__ void k_init() {
    int i = blockIdx.x * blockDim.x + threadIdx.x;
    if (i < NROW) { g_amin[i] = 0x7F800000u; g_ccnt[i] = 0u; }
    if (i < NCODE) g_cnt[i] = 0u;
    if (i == 0) g_mse = 0.0;
}

// One warp per vector: squared L2 norms (double accum, rounded to fp32).
// NOTE: summation order unchanged since R1 (strided d=lane,+32) — the exact
// verify path depends on this A being stable across rounds.
__global__ void k_norms(const float* __restrict__ X, const float* __restrict__ E) {
    int gwarp = (blockIdx.x * blockDim.x + threadIdx.x) >> 5;
    int lane = threadIdx.x & 31;
    const float* base; float* out; int nid;
    if (gwarp < NROW)      { base = X + (size_t)gwarp * DIM; out = g_rowsq; nid = gwarp; }
    else if (gwarp < NROW + NCODE) { nid = gwarp - NROW; base = E + (size_t)nid * DIM; out = g_csq; }
    else return;
    double s = 0.0;
    #pragma unroll 4
    for (int d = lane; d < DIM; d += 32) { float v = base[d]; s += (double)v * (double)v; }
    #pragma unroll
    for (int o = 16; o > 0; o >>= 1) s += __shfl_down_sync(0xffffffffu, s, o);
    if (lane == 0) out[nid] = (float)s;
}

// ---------------------------------------------------------------------------
// Phase 1: int8 mma.sync GEMM filter, 2 CTAs/SM.
// CTA = 128 rows x 128 codes, 256 threads (8 warps, 4x2), warp tile 32x64 —
// per-warp inner loop byte-identical to the proven R6 engine.
// K-tile=128 s8 (128B sw128 rows), 3-stage cp.async, epilogue AFTER mainloop.
#define NKIT   4                     // 512 / 128
#define A_ST   (128 * 128)           // 16384
#define B_ST   (128 * 128)           // 16384
#define STG_BY (A_ST + B_ST)         // 32768
#define NSTG   3
#define OFF_RM (NSTG * STG_BY)       // 98304 rowmin[128] u32
#define OFF_TH (OFF_RM + 512)        // thr[128] f32
#define OFF_CS (OFF_TH + 512)        // csq_s[128] f32
#define OFF_RS (OFF_CS + 512)        // rowsq_s[128] f32
#define GSMEM  (OFF_RS + 512)        // 100352 -> 2 CTAs/SM

__global__ __launch_bounds__(256, 2)
void k_gemm_s8() {
    extern __shared__ char sm[];
    const int tid = threadIdx.x;
    const int wid = tid >> 5, lane = tid & 31;
    const int warp_m = wid & 3, warp_n = wid >> 2;     // 4x2 warps
    const int grp = lane >> 2, tid4 = lane & 3;
    const int bm = blockIdx.x * 128, bn = blockIdx.y * 128;   // x = row tile
    const unsigned base = smem_u32(sm);

    unsigned* rowmin = (unsigned*)(sm + OFF_RM);
    float* thr_s   = (float*)(sm + OFF_TH);
    float* csq_s   = (float*)(sm + OFF_CS);
    float* rowsq_s = (float*)(sm + OFF_RS);

    if (tid < 128) {
        rowmin[tid] = 0xFFFFFFFFu;
        rowsq_s[tid] = g_rowsq[bm + tid];
        csq_s[tid] = g_csq[bn + tid];
    }

    const char* XA = (const char*)g_Xq + (size_t)bm * DIM;
    const char* EB = (const char*)g_Eq + (size_t)bn * DIM;

    int acc[2][8][4];
    #pragma unroll
    for (int mi = 0; mi < 2; mi++)
        #pragma unroll
        for (int ni = 0; ni < 8; ni++)
            #pragma unroll
            for (int c = 0; c < 4; c++) acc[mi][ni][c] = 0;

    auto issue = [&](int stage, int kt) {
        const int k0 = kt * 128;                      // byte offset in row
        const unsigned sA = base + stage * STG_BY;
        const unsigned sB = sA + A_ST;
        #pragma unroll
        for (int i = 0; i < 4; i++) {                 // A: 1024 chunks of 16B
            int u = tid + (i << 8);
            int r = u >> 3, q = u & 7;
            cp_async16(sA + sw128(r * 128 + q * 16), XA + (size_t)r * DIM + k0 + q * 16);
        }
        #pragma unroll
        for (int i = 0; i < 4; i++) {                 // B: 1024 chunks
            int u = tid + (i << 8);
            int r = u >> 3, q = u & 7;
            cp_async16(sB + sw128(r * 128 + q * 16), EB + (size_t)r * DIM + k0 + q * 16);
        }
        cp_commit();
    };

    issue(0, 0); issue(1, 1);

    // ldmatrix lane-constant row/byte offsets (identical mapping to R6)
    const int a_row = warp_m * 32 + (lane & 15);          // + mi*16
    const int a_kb  = (lane >> 4) * 16;
    const int b_row = warp_n * 64 + (lane & 7) + ((lane >> 4) << 3);   // + nj*16
    const int b_kb  = ((lane >> 3) & 1) * 16;

    for (int kt = 0; kt < NKIT; kt++) {
        if (kt == NKIT - 1) cp_wait0(); else cp_wait1();
        __syncthreads();
        if (kt + 2 < NKIT) issue((kt + 2) % NSTG, kt + 2);

        const unsigned sA = base + (kt % NSTG) * STG_BY;
        const unsigned sB = sA + A_ST;

        #pragma unroll
        for (int ks = 0; ks < 4; ks++) {              // 4 x k32 per 128B row
            const int kb = ks * 32;
            unsigned a[2][4], b[8][2];
            #pragma unroll
            for (int mi = 0; mi < 2; mi++)
                ldsm_x4(a[mi][0], a[mi][1], a[mi][2], a[mi][3],
                        sA + sw128((a_row + mi * 16) * 128 + kb + a_kb));
            #pragma unroll
            for (int nj = 0; nj < 4; nj++) {
                unsigned r0, r1, r2, r3;
                ldsm_x4(r0, r1, r2, r3,
                        sB + sw128((b_row + nj * 16) * 128 + kb + b_kb));
                b[nj * 2][0] = r0;     b[nj * 2][1] = r1;
                b[nj * 2 + 1][0] = r2; b[nj * 2 + 1][1] = r3;
            }
            #pragma unroll
            for (int mi = 0; mi < 2; mi++)
                #pragma unroll
                for (int ni = 0; ni < 8; ni++)
                    mma16832s8(acc[mi][ni], a[mi], b[ni]);
        }
        __syncthreads();
    }

    // --- epilogue pass 1: per-row local min of approx dist ---
    #pragma unroll
    for (int mi = 0; mi < 2; mi++) {
        const int r0 = warp_m * 32 + mi * 16 + grp;
        const float A0 = rowsq_s[r0], A1 = rowsq_s[r0 + 8];
        float m0 = 3.4e38f, m1 = 3.4e38f;
        #pragma unroll
        for (int ni = 0; ni < 8; ni++) {
            const int n = warp_n * 64 + ni * 8 + tid4 * 2;
            const float B0 = csq_s[n], B1 = csq_s[n + 1];
            const int* cc = acc[mi][ni];
            m0 = fminf(m0, fminf(A0 + B0 - TWOINV * (float)cc[0],
                                 A0 + B1 - TWOINV * (float)cc[1]));
            m1 = fminf(m1, fminf(A1 + B0 - TWOINV * (float)cc[2],
                                 A1 + B1 - TWOINV * (float)cc[3]));
        }
        atomicMin(&rowmin[r0], __float_as_uint(m0));       // dists > 0
        atomicMin(&rowmin[r0 + 8], __float_as_uint(m1));
    }
    __syncthreads();
    if (tid < 128) {
        unsigned mine = rowmin[tid];
        g_tilemin[(size_t)(bm + tid) * NTILE + blockIdx.y] = mine;   // per-tile min
        unsigned old = atomicMin(&g_amin[bm + tid], mine);
        thr_s[tid] = __uint_as_float(old < mine ? old : mine) + EPS_F;
    }
    __syncthreads();

    // --- epilogue pass 2: append (dist,code) within EPS of running min ---
    #pragma unroll
    for (int mi = 0; mi < 2; mi++) {
        const int r0 = warp_m * 32 + mi * 16 + grp;
        const float A0 = rowsq_s[r0], A1 = rowsq_s[r0 + 8];
        const float t0 = thr_s[r0], t1 = thr_s[r0 + 8];
        #pragma unroll
        for (int ni = 0; ni < 8; ni++) {
            const int n = warp_n * 64 + ni * 8 + tid4 * 2;
            const float B0 = csq_s[n], B1 = csq_s[n + 1];
            const int* cc = acc[mi][ni];
            float d00 = A0 + B0 - TWOINV * (float)cc[0];
            float d01 = A0 + B1 - TWOINV * (float)cc[1];
            float d10 = A1 + B0 - TWOINV * (float)cc[2];
            float d11 = A1 + B1 - TWOINV * (float)cc[3];
            if (d00 < t0) { unsigned p = atomicAdd(&g_ccnt[bm + r0], 1u);
                if (p < CAP) g_cand64[(size_t)(bm + r0) * CAP + p] =
                    ((unsigned long long)__float_as_uint(d00) << 32) | (unsigned)(bn + n); }
            if (d01 < t0) { unsigned p = atomicAdd(&g_ccnt[bm + r0], 1u);
                if (p < CAP) g_cand64[(size_t)(bm + r0) * CAP + p] =
                    ((unsigned long long)__float_as_uint(d01) << 32) | (unsigned)(bn + n + 1); }
            if (d10 < t1) { unsigned p = atomicAdd(&g_ccnt[bm + r0 + 8], 1u);
                if (p < CAP) g_cand64[(size_t)(bm + r0 + 8) * CAP + p] =
                    ((unsigned long long)__float_as_uint(d10) << 32) | (unsigned)(bn + n); }
            if (d11 < t1) { unsigned p = atomicAdd(&g_ccnt[bm + r0 + 8], 1u);
                if (p < CAP) g_cand64[(size_t)(bm + r0 + 8) * CAP + p] =
                    ((unsigned long long)__float_as_uint(d11) << 32) | (unsigned)(bn + n + 1); }
        }
    }
}

// ---------------------------------------------------------------------------
// Final per-row threshold from tile minima: thr = min over 64 tiles + EPS.
__global__ void k_thresh() {
    int r = blockIdx.x * blockDim.x + threadIdx.x;
    if (r >= NROW) return;
    unsigned m = 0xFFFFFFFFu;
    #pragma unroll 8
    for (int t = 0; t < NTILE; t++) {
        unsigned v = g_tilemin[(size_t)r * NTILE + t];
        if (v < m) m = v;
    }
    g_thr[r] = __uint_as_float(m) + EPS_F;
}

// ---------------------------------------------------------------------------
// Phase 2: filter stored candidates by the FINAL threshold, then exact
// re-verification bit-identical to R1's fp32 path (sequential ascending-k
// FMA dot; packed-key min = smallest dist then smallest index).
__global__ void k_select(const float* __restrict__ X, const float* __restrict__ E) {
    int gid = blockIdx.x * blockDim.x + threadIdx.x;
    int r = gid >> 3, slot = gid & 7;
    if (r >= NROW) return;
    unsigned cnt = g_ccnt[r];
    const float thr = g_thr[r];
    const float* x = X + (size_t)r * DIM;
    const float A = g_rowsq[r];
    unsigned long long best = 0xFFFFFFFFFFFFFFFFULL;
    if (cnt <= CAP) {
        for (unsigned i = slot; i < cnt; i += 8) {
            unsigned long long kc = g_cand64[(size_t)r * CAP + i];
            if (__uint_as_float((unsigned)(kc >> 32)) >= thr) continue;
            int c = (int)(kc & 0xFFFFu);
            const float* e = E + (size_t)c * DIM;
            float acc = 0.0f;
            #pragma unroll 8
            for (int k = 0; k < DIM; k++) acc = fmaf(x[k], e[k], acc);
            float dist = __fsub_rn(__fadd_rn(A, g_csq[c]), 2.0f * acc);
            unsigned long long key =
                ((unsigned long long)__float_as_uint(dist) << 32) | (unsigned)c;
            if (key < best) best = key;
        }
    } else {
        // overflow fallback (expected ~never): scan tiles whose min < thr
        for (int t = 0; t < NTILE; t++) {
            if (__uint_as_float(g_tilemin[(size_t)r * NTILE + t]) >= thr) continue;
            for (int c = t * 128 + slot; c < (t + 1) * 128; c += 8) {
                const float* e = E + (size_t)c * DIM;
                float acc = 0.0f;
                #pragma unroll 8
                for (int k = 0; k < DIM; k++) acc = fmaf(x[k], e[k], acc);
                float dist = __fsub_rn(__fadd_rn(A, g_csq[c]), 2.0f * acc);
                unsigned long long key =
                    ((unsigned long long)__float_as_uint(dist) << 32) | (unsigned)c;
                if (key < best) best = key;
            }
        }
    }
    #pragma unroll
    for (int o = 4; o > 0; o >>= 1) {
        unsigned long long t = __shfl_down_sync(0xffffffffu, best, o, 8);
        if (t < best) best = t;
    }
    if (slot == 0) {
        int idx = (int)(unsigned)(best & 0xFFFFFFFFu);
        g_idx[r] = idx;
        atomicAdd(&g_cnt[idx], 1u);
    }
}

// ---------------------------------------------------------------------------
__global__ void k_quant_loss(const float* __restrict__ X, const float* __restrict__ E,
                             float* __restrict__ q_out) {
    __shared__ double sred[8];
    int i = blockIdx.x * blockDim.x + threadIdx.x;
    int row = i >> 9;
    int d = i & 511;
    int idx = g_idx[row];
    float q = E[(size_t)idx * DIM + d];
    float x = X[i];
    float diff = __fsub_rn(q, x);
    q_out[i] = __fadd_rn(x, diff);
    double local = (double)diff * (double)diff;
    #pragma unroll
    for (int o = 16; o > 0; o >>= 1) local += __shfl_down_sync(0xffffffffu, local, o);
    int lane = threadIdx.x & 31, w = threadIdx.x >> 5;
    if (lane == 0) sred[w] = local;
    __syncthreads();
    if (w == 0) {
        double v = (lane < 8) ? sred[lane] : 0.0;
        #pragma unroll
        for (int o = 4; o > 0; o >>= 1) v += __shfl_down_sync(0xffffffffu, v, o);
        if (lane == 0) atomicAdd(&g_mse, v);
    }
}

// Zero encodings: grid-stride streaming stores; head/tail scalars.
__global__ void k_zero_enc(float* __restrict__ p) {
    const size_t n4 = 33554431;                    // (NROW*NCODE - 4) / 4
    float4* p4 = (float4*)(p + 2);
    size_t stride = (size_t)gridDim.x * blockDim.x;
    float4 z = make_float4(0.f, 0.f, 0.f, 0.f);
    for (size_t i = blockIdx.x * (size_t)blockDim.x + threadIdx.x; i < n4; i += stride)
        __stcs(&p4[i], z);
    if (blockIdx.x == 0 && threadIdx.x == 0) {
        p[0] = 0.f; p[1] = 0.f;
        p[(size_t)NROW * NCODE - 2] = 0.f; p[(size_t)NROW * NCODE - 1] = 0.f;
    }
}

__global__ void k_ones(float* __restrict__ enc) {
    int i = blockIdx.x * blockDim.x + threadIdx.x;
    if (i < NROW) enc[(size_t)i * NCODE + g_idx[i]] = 1.0f;
}

__global__ void k_final(float* __restrict__ out) {
    __shared__ double sred[8];
    int t = threadIdx.x;
    double h = 0.0;
    for (int k = t; k < NCODE; k += 256) {
        float p = (float)g_cnt[k] * (1.0f / 16384.0f);
        float arg = __fadd_rn(p, 1e-10f);
        h += (double)p * log((double)arg);
    }
    #pragma unroll
    for (int o = 16; o > 0; o >>= 1) h += __shfl_down_sync(0xffffffffu, h, o);
    int lane = t & 31, w = t >> 5;
    if (lane == 0) sred[w] = h;
    __syncthreads();
    if (w == 0) {
        double v = (lane < 8) ? sred[lane] : 0.0;
        #pragma unroll
        for (int o = 4; o > 0; o >>= 1) v += __shfl_down_sync(0xffffffffu, v, o);
        if (lane == 0) {
            out[OFF_PERP] = (float)exp(-v);
            float m = (float)(g_mse / (double)QELEMS);
            out[OFF_LOSS] = __fadd_rn(m, 0.25f * m);
        }
    }
}

// ---------------------------------------------------------------------------
extern "C" void kernel_launch(void* const* d_in, const int* in_sizes, int n_in,
                              void* d_out, int out_size) {
    const float* X = (const float*)d_in[0];   // [64,256,512] fp32
    const float* E = (const float*)d_in[1];   // [8192,512] fp32
    float* out = (float*)d_out;

    static int inited = 0;
    static cudaStream_t s1;
    static cudaEvent_t ev_fork, ev_join;
    if (!inited) {
        cudaFuncSetAttribute(k_gemm_s8, cudaFuncAttributeMaxDynamicSharedMemorySize, GSMEM);
        cudaStreamCreateWithFlags(&s1, cudaStreamNonBlocking);
        cudaEventCreateWithFlags(&ev_fork, cudaEventDisableTiming);
        cudaEventCreateWithFlags(&ev_join, cudaEventDisableTiming);
        inited = 1;
    }

    // Launch order fixed so the GEMM is chronological launch #4 (ncu target).
    k_conv<<<12288, 256>>>(X, E);                  // #1
    k_init<<<64, 256>>>();                         // #2
    k_norms<<<3072, 256>>>(X, E);                  // #3

    dim3 grid(NROW / 128, NCODE / 128);            // (128, 64), 2 CTAs/SM
    k_gemm_s8<<<grid, 256, GSMEM>>>();             // #4

    // Encodings zero-fill, concurrent with the tail kernels.
    cudaEventRecord(ev_fork, 0);
    cudaStreamWaitEvent(s1, ev_fork, 0);
    k_zero_enc<<<2048, 256, 0, s1>>>(out + OFF_ENC);   // #5 (stream s1)
    cudaEventRecord(ev_join, s1);

    k_thresh<<<64, 256>>>();                       // #6
    k_select<<<(NROW * 8) / 256, 256>>>(X, E);     // #7
    k_quant_loss<<<QELEMS / 256, 256>>>(X, E, out + OFF_Q);   // #8

    cudaStreamWaitEvent(0, ev_join, 0);
    k_ones<<<64, 256>>>(out + OFF_ENC);            // #9
    k_final<<<1, 256>>>(out);                      // #10
}

// round 14
// speedup vs baseline: 1.0761x; 1.0080x over previous
#include <cuda_runtime.h>
#include <math.h>

// Problem shape
#define NROW   16384     // 64*256 flattened input vectors
#define NCODE  8192      // codebook entries
#define DIM    512       // embedding dim
#define NTILE  64        // NCODE / 128
#define QELEMS (NROW * DIM)          // 8388608
#define OFF_LOSS 0
#define OFF_Q    1
#define OFF_PERP (1 + QELEMS)        // 8388609
#define OFF_ENC  (2 + QELEMS)        // 8388610

#define CAP      256                 // per-row candidate capacity (u64 list)
#define EPS_F    8e-4f
#define SX       24.0f
#define SE       1040384.0f          // 127 / (1/8192)
#define TWOINV   (2.0f / (SX * SE))

// Scratch (device globals; no allocations allowed)
__device__ int g_idx[NROW];
__device__ unsigned int g_cnt[NCODE];
__device__ float g_rowsq[NROW];       // A_m = fp32(sum x^2)
__device__ float g_csq[NCODE];        // B_k = fp32(sum e^2)
__device__ double g_mse;
__device__ unsigned g_amin[NROW];     // running approx min (float bits)
__device__ unsigned g_ccnt[NROW];     // candidate counts
__device__ unsigned g_tilemin[(size_t)NROW * NTILE];   // per (row, n-tile) min bits
__device__ float g_thr[NROW];         // final threshold
__device__ unsigned long long g_cand64[(size_t)NROW * CAP];  // (dist bits, code)
__device__ unsigned g_Xq[(size_t)NROW * DIM / 4];    // s8 packed
__device__ unsigned g_Eq[(size_t)NCODE * DIM / 4];   // s8 packed

// ---------------------------------------------------------------------------
__device__ __forceinline__ unsigned smem_u32(const void* p) {
    unsigned a;
    asm("{ .reg .u64 t; cvta.to.shared.u64 t, %1; cvt.u32.u64 %0, t; }" : "=r"(a) : "l"(p));
    return a;
}
__device__ __forceinline__ void cp_async16(unsigned dst, const void* src) {
    asm volatile("cp.async.cg.shared.global [%0], [%1], 16;" :: "r"(dst), "l"(src) : "memory");
}
__device__ __forceinline__ void cp_commit() {
    asm volatile("cp.async.commit_group;" ::: "memory");
}
__device__ __forceinline__ void cp_wait1() {
    asm volatile("cp.async.wait_group 1;" ::: "memory");
}
__device__ __forceinline__ void cp_wait0() {
    asm volatile("cp.async.wait_group 0;" ::: "memory");
}
__device__ __forceinline__ void ldsm_x4(unsigned& r0, unsigned& r1, unsigned& r2, unsigned& r3,
                                        unsigned addr) {
    asm volatile("ldmatrix.sync.aligned.m8n8.x4.shared.b16 {%0,%1,%2,%3}, [%4];"
                 : "=r"(r0), "=r"(r1), "=r"(r2), "=r"(r3) : "r"(addr));
}
__device__ __forceinline__ void mma16832s8(int* c, const unsigned* a, const unsigned* b) {
    asm volatile("mma.sync.aligned.m16n8k32.row.col.s32.s8.s8.s32 "
                 "{%0,%1,%2,%3}, {%4,%5,%6,%7}, {%8,%9}, {%0,%1,%2,%3};"
                 : "+r"(c[0]), "+r"(c[1]), "+r"(c[2]), "+r"(c[3])
                 : "r"(a[0]), "r"(a[1]), "r"(a[2]), "r"(a[3]), "r"(b[0]), "r"(b[1]));
}
__device__ __forceinline__ unsigned sw128(unsigned off) { return off ^ ((off >> 3) & 0x70u); }
__device__ __forceinline__ int q8(float v, float s) {
    int q = __float2int_rn(v * s);
    return q > 127 ? 127 : (q < -127 ? -127 : q);
}

// ---------------------------------------------------------------------------
// Fused int8 quantization of X and E (filter precision only).
__global__ void k_conv(const float* __restrict__ X, const float* __restrict__ E) {
    int i = blockIdx.x * blockDim.x + threadIdx.x;
    if (i < QELEMS / 4) {
        float4 v = ((const float4*)X)[i];
        g_Xq[i] = (unsigned)(q8(v.x, SX) & 255) | ((unsigned)(q8(v.y, SX) & 255) << 8) |
                  ((unsigned)(q8(v.z, SX) & 255) << 16) | ((unsigned)(q8(v.w, SX) & 255) << 24);
    } else {
        int j = i - QELEMS / 4;
        if (j >= (NCODE * DIM) / 4) return;
        float4 v = ((const float4*)E)[j];
        g_Eq[j] = (unsigned)(q8(v.x, SE) & 255) | ((unsigned)(q8(v.y, SE) & 255) << 8) |
                  ((unsigned)(q8(v.z, SE) & 255) << 16) | ((unsigned)(q8(v.w, SE) & 255) << 24);
    }
}

__global__ void k_init() {
    int i = blockIdx.x * blockDim.x + threadIdx.x;
    if (i < NROW) { g_amin[i] = 0x7F800000u; g_ccnt[i] = 0u; }
    if (i < NCODE) g_cnt[i] = 0u;
    if (i == 0) g_mse = 0.0;
}

// One warp per vector: squared L2 norms (double accum, rounded to fp32).
__global__ void k_norms(const float* __restrict__ X, const float* __restrict__ E) {
    int gwarp = (blockIdx.x * blockDim.x + threadIdx.x) >> 5;
    int lane = threadIdx.x & 31;
    const float* base; float* out; int nid;
    if (gwarp < NROW)      { base = X + (size_t)gwarp * DIM; out = g_rowsq; nid = gwarp; }
    else if (gwarp < NROW + NCODE) { nid = gwarp - NROW; base = E + (size_t)nid * DIM; out = g_csq; }
    else return;
    double s = 0.0;
    #pragma unroll 4
    for (int d = lane; d < DIM; d += 32) { float v = base[d]; s += (double)v * (double)v; }
    #pragma unroll
    for (int o = 16; o > 0; o >>= 1) s += __shfl_down_sync(0xffffffffu, s, o);
    if (lane == 0) out[nid] = (float)s;
}

// ---------------------------------------------------------------------------
// Phase 1: int8 mma.sync GEMM filter, 2 CTAs/SM (measured 256us, tensor 49%).
#define NKIT   4                     // 512 / 128
#define A_ST   (128 * 128)           // 16384
#define B_ST   (128 * 128)           // 16384
#define STG_BY (A_ST + B_ST)         // 32768
#define NSTG   3
#define OFF_RM (NSTG * STG_BY)       // 98304 rowmin[128] u32
#define OFF_TH (OFF_RM + 512)        // thr[128] f32
#define OFF_CS (OFF_TH + 512)        // csq_s[128] f32
#define OFF_RS (OFF_CS + 512)        // rowsq_s[128] f32
#define GSMEM  (OFF_RS + 512)        // 100352 -> 2 CTAs/SM

__global__ __launch_bounds__(256, 2)
void k_gemm_s8() {
    extern __shared__ char sm[];
    const int tid = threadIdx.x;
    const int wid = tid >> 5, lane = tid & 31;
    const int warp_m = wid & 3, warp_n = wid >> 2;     // 4x2 warps
    const int grp = lane >> 2, tid4 = lane & 3;
    const int bm = blockIdx.x * 128, bn = blockIdx.y * 128;   // x = row tile
    const unsigned base = smem_u32(sm);

    unsigned* rowmin = (unsigned*)(sm + OFF_RM);
    float* thr_s   = (float*)(sm + OFF_TH);
    float* csq_s   = (float*)(sm + OFF_CS);
    float* rowsq_s = (float*)(sm + OFF_RS);

    if (tid < 128) {
        rowmin[tid] = 0xFFFFFFFFu;
        rowsq_s[tid] = g_rowsq[bm + tid];
        csq_s[tid] = g_csq[bn + tid];
    }

    const char* XA = (const char*)g_Xq + (size_t)bm * DIM;
    const char* EB = (const char*)g_Eq + (size_t)bn * DIM;

    int acc[2][8][4];
    #pragma unroll
    for (int mi = 0; mi < 2; mi++)
        #pragma unroll
        for (int ni = 0; ni < 8; ni++)
            #pragma unroll
            for (int c = 0; c < 4; c++) acc[mi][ni][c] = 0;

    auto issue = [&](int stage, int kt) {
        const int k0 = kt * 128;                      // byte offset in row
        const unsigned sA = base + stage * STG_BY;
        const unsigned sB = sA + A_ST;
        #pragma unroll
        for (int i = 0; i < 4; i++) {                 // A: 1024 chunks of 16B
            int u = tid + (i << 8);
            int r = u >> 3, q = u & 7;
            cp_async16(sA + sw128(r * 128 + q * 16), XA + (size_t)r * DIM + k0 + q * 16);
        }
        #pragma unroll
        for (int i = 0; i < 4; i++) {                 // B: 1024 chunks
            int u = tid + (i << 8);
            int r = u >> 3, q = u & 7;
            cp_async16(sB + sw128(r * 128 + q * 16), EB + (size_t)r * DIM + k0 + q * 16);
        }
        cp_commit();
    };

    issue(0, 0); issue(1, 1);

    const int a_row = warp_m * 32 + (lane & 15);          // + mi*16
    const int a_kb  = (lane >> 4) * 16;
    const int b_row = warp_n * 64 + (lane & 7) + ((lane >> 4) << 3);   // + nj*16
    const int b_kb  = ((lane >> 3) & 1) * 16;

    for (int kt = 0; kt < NKIT; kt++) {
        if (kt == NKIT - 1) cp_wait0(); else cp_wait1();
        __syncthreads();
        if (kt + 2 < NKIT) issue((kt + 2) % NSTG, kt + 2);

        const unsigned sA = base + (kt % NSTG) * STG_BY;
        const unsigned sB = sA + A_ST;

        #pragma unroll
        for (int ks = 0; ks < 4; ks++) {              // 4 x k32 per 128B row
            const int kb = ks * 32;
            unsigned a[2][4], b[8][2];
            #pragma unroll
            for (int mi = 0; mi < 2; mi++)
                ldsm_x4(a[mi][0], a[mi][1], a[mi][2], a[mi][3],
                        sA + sw128((a_row + mi * 16) * 128 + kb + a_kb));
            #pragma unroll
            for (int nj = 0; nj < 4; nj++) {
                unsigned r0, r1, r2, r3;
                ldsm_x4(r0, r1, r2, r3,
                        sB + sw128((b_row + nj * 16) * 128 + kb + b_kb));
                b[nj * 2][0] = r0;     b[nj * 2][1] = r1;
                b[nj * 2 + 1][0] = r2; b[nj * 2 + 1][1] = r3;
            }
            #pragma unroll
            for (int mi = 0; mi < 2; mi++)
                #pragma unroll
                for (int ni = 0; ni < 8; ni++)
                    mma16832s8(acc[mi][ni], a[mi], b[ni]);
        }
        __syncthreads();
    }

    // --- epilogue pass 1: per-row local min of approx dist ---
    #pragma unroll
    for (int mi = 0; mi < 2; mi++) {
        const int r0 = warp_m * 32 + mi * 16 + grp;
        const float A0 = rowsq_s[r0], A1 = rowsq_s[r0 + 8];
        float m0 = 3.4e38f, m1 = 3.4e38f;
        #pragma unroll
        for (int ni = 0; ni < 8; ni++) {
            const int n = warp_n * 64 + ni * 8 + tid4 * 2;
            const float B0 = csq_s[n], B1 = csq_s[n + 1];
            const int* cc = acc[mi][ni];
            m0 = fminf(m0, fminf(A0 + B0 - TWOINV * (float)cc[0],
                                 A0 + B1 - TWOINV * (float)cc[1]));
            m1 = fminf(m1, fminf(A1 + B0 - TWOINV * (float)cc[2],
                                 A1 + B1 - TWOINV * (float)cc[3]));
        }
        atomicMin(&rowmin[r0], __float_as_uint(m0));       // dists > 0
        atomicMin(&rowmin[r0 + 8], __float_as_uint(m1));
    }
    __syncthreads();
    if (tid < 128) {
        unsigned mine = rowmin[tid];
        g_tilemin[(size_t)(bm + tid) * NTILE + blockIdx.y] = mine;   // per-tile min
        unsigned old = atomicMin(&g_amin[bm + tid], mine);
        thr_s[tid] = __uint_as_float(old < mine ? old : mine) + EPS_F;
    }
    __syncthreads();

    // --- epilogue pass 2: append (dist,code) within EPS of running min ---
    #pragma unroll
    for (int mi = 0; mi < 2; mi++) {
        const int r0 = warp_m * 32 + mi * 16 + grp;
        const float A0 = rowsq_s[r0], A1 = rowsq_s[r0 + 8];
        const float t0 = thr_s[r0], t1 = thr_s[r0 + 8];
        #pragma unroll
        for (int ni = 0; ni < 8; ni++) {
            const int n = warp_n * 64 + ni * 8 + tid4 * 2;
            const float B0 = csq_s[n], B1 = csq_s[n + 1];
            const int* cc = acc[mi][ni];
            float d00 = A0 + B0 - TWOINV * (float)cc[0];
            float d01 = A0 + B1 - TWOINV * (float)cc[1];
            float d10 = A1 + B0 - TWOINV * (float)cc[2];
            float d11 = A1 + B1 - TWOINV * (float)cc[3];
            if (d00 < t0) { unsigned p = atomicAdd(&g_ccnt[bm + r0], 1u);
                if (p < CAP) g_cand64[(size_t)(bm + r0) * CAP + p] =
                    ((unsigned long long)__float_as_uint(d00) << 32) | (unsigned)(bn + n); }
            if (d01 < t0) { unsigned p = atomicAdd(&g_ccnt[bm + r0], 1u);
                if (p < CAP) g_cand64[(size_t)(bm + r0) * CAP + p] =
                    ((unsigned long long)__float_as_uint(d01) << 32) | (unsigned)(bn + n + 1); }
            if (d10 < t1) { unsigned p = atomicAdd(&g_ccnt[bm + r0 + 8], 1u);
                if (p < CAP) g_cand64[(size_t)(bm + r0 + 8) * CAP + p] =
                    ((unsigned long long)__float_as_uint(d10) << 32) | (unsigned)(bn + n); }
            if (d11 < t1) { unsigned p = atomicAdd(&g_ccnt[bm + r0 + 8], 1u);
                if (p < CAP) g_cand64[(size_t)(bm + r0 + 8) * CAP + p] =
                    ((unsigned long long)__float_as_uint(d11) << 32) | (unsigned)(bn + n + 1); }
        }
    }
}

// ---------------------------------------------------------------------------
// Final per-row threshold from tile minima: thr = min over 64 tiles + EPS.
__global__ void k_thresh() {
    int r = blockIdx.x * blockDim.x + threadIdx.x;
    if (r >= NROW) return;
    unsigned m = 0xFFFFFFFFu;
    #pragma unroll 8
    for (int t = 0; t < NTILE; t++) {
        unsigned v = g_tilemin[(size_t)r * NTILE + t];
        if (v < m) m = v;
    }
    g_thr[r] = __uint_as_float(m) + EPS_F;
}

// ---------------------------------------------------------------------------
// Phase 2: filter stored candidates by the FINAL threshold, then exact
// re-verification bit-identical to R1's fp32 path.
__global__ void k_select(const float* __restrict__ X, const float* __restrict__ E) {
    int gid = blockIdx.x * blockDim.x + threadIdx.x;
    int r = gid >> 3, slot = gid & 7;
    if (r >= NROW) return;
    unsigned cnt = g_ccnt[r];
    const float thr = g_thr[r];
    const float* x = X + (size_t)r * DIM;
    const float A = g_rowsq[r];
    unsigned long long best = 0xFFFFFFFFFFFFFFFFULL;
    if (cnt <= CAP) {
        for (unsigned i = slot; i < cnt; i += 8) {
            unsigned long long kc = g_cand64[(size_t)r * CAP + i];
            if (__uint_as_float((unsigned)(kc >> 32)) >= thr) continue;
            int c = (int)(kc & 0xFFFFu);
            const float* e = E + (size_t)c * DIM;
            float acc = 0.0f;
            #pragma unroll 8
            for (int k = 0; k < DIM; k++) acc = fmaf(x[k], e[k], acc);
            float dist = __fsub_rn(__fadd_rn(A, g_csq[c]), 2.0f * acc);
            unsigned long long key =
                ((unsigned long long)__float_as_uint(dist) << 32) | (unsigned)c;
            if (key < best) best = key;
        }
    } else {
        // overflow fallback (expected ~never): scan tiles whose min < thr
        for (int t = 0; t < NTILE; t++) {
            if (__uint_as_float(g_tilemin[(size_t)r * NTILE + t]) >= thr) continue;
            for (int c = t * 128 + slot; c < (t + 1) * 128; c += 8) {
                const float* e = E + (size_t)c * DIM;
                float acc = 0.0f;
                #pragma unroll 8
                for (int k = 0; k < DIM; k++) acc = fmaf(x[k], e[k], acc);
                float dist = __fsub_rn(__fadd_rn(A, g_csq[c]), 2.0f * acc);
                unsigned long long key =
                    ((unsigned long long)__float_as_uint(dist) << 32) | (unsigned)c;
                if (key < best) best = key;
            }
        }
    }
    #pragma unroll
    for (int o = 4; o > 0; o >>= 1) {
        unsigned long long t = __shfl_down_sync(0xffffffffu, best, o, 8);
        if (t < best) best = t;
    }
    if (slot == 0) {
        int idx = (int)(unsigned)(best & 0xFFFFFFFFu);
        g_idx[r] = idx;
        atomicAdd(&g_cnt[idx], 1u);
    }
}

// ---------------------------------------------------------------------------
__global__ void k_quant_loss(const float* __restrict__ X, const float* __restrict__ E,
                             float* __restrict__ q_out) {
    __shared__ double sred[8];
    int i = blockIdx.x * blockDim.x + threadIdx.x;
    int row = i >> 9;
    int d = i & 511;
    int idx = g_idx[row];
    float q = E[(size_t)idx * DIM + d];
    float x = X[i];
    float diff = __fsub_rn(q, x);
    q_out[i] = __fadd_rn(x, diff);
    double local = (double)diff * (double)diff;
    #pragma unroll
    for (int o = 16; o > 0; o >>= 1) local += __shfl_down_sync(0xffffffffu, local, o);
    int lane = threadIdx.x & 31, w = threadIdx.x >> 5;
    if (lane == 0) sred[w] = local;
    __syncthreads();
    if (w == 0) {
        double v = (lane < 8) ? sred[lane] : 0.0;
        #pragma unroll
        for (int o = 4; o > 0; o >>= 1) v += __shfl_down_sync(0xffffffffu, v, o);
        if (lane == 0) atomicAdd(&g_mse, v);
    }
}

// ---------------------------------------------------------------------------
// Single-pass one-hot encodings write: enc[r][c] = (c == idx[r]).
// Body as float4 on (p+2) 16B-aligned pointer; per-component row/col decode
// (rows span 8192 cols so the idx load is L1-resident per warp).
__global__ void k_encodings(float* __restrict__ p) {
    const size_t n4 = 33554431;                    // (NROW*NCODE - 4) / 4
    float4* p4 = (float4*)(p + 2);
    size_t stride = (size_t)gridDim.x * blockDim.x;
    for (size_t i = blockIdx.x * (size_t)blockDim.x + threadIdx.x; i < n4; i += stride) {
        size_t e = i * 4 + 2;                      // global enc element of .x
        int r = (int)(e >> 13);
        int c = (int)(e & 8191);
        float4 v;
        if (c <= 8188) {                           // all 4 in same row (common)
            int idx = g_idx[r];
            v.x = (c == idx) ? 1.0f : 0.0f;
            v.y = (c + 1 == idx) ? 1.0f : 0.0f;
            v.z = (c + 2 == idx) ? 1.0f : 0.0f;
            v.w = (c + 3 == idx) ? 1.0f : 0.0f;
        } else {
            size_t e1 = e + 1, e2 = e + 2, e3 = e + 3;
            v.x = ((int)(e & 8191) == g_idx[e >> 13]) ? 1.0f : 0.0f;
            v.y = ((int)(e1 & 8191) == g_idx[e1 >> 13]) ? 1.0f : 0.0f;
            v.z = ((int)(e2 & 8191) == g_idx[e2 >> 13]) ? 1.0f : 0.0f;
            v.w = ((int)(e3 & 8191) == g_idx[e3 >> 13]) ? 1.0f : 0.0f;
        }
        p4[i] = v;
    }
    if (blockIdx.x == 0 && threadIdx.x == 0) {
        // head: elements 0,1 of row 0; tail: last 2 elements of last row
        int i0 = g_idx[0];
        p[0] = (i0 == 0) ? 1.0f : 0.0f;
        p[1] = (i0 == 1) ? 1.0f : 0.0f;
        int il = g_idx[NROW - 1];
        p[(size_t)NROW * NCODE - 2] = (il == 8190) ? 1.0f : 0.0f;
        p[(size_t)NROW * NCODE - 1] = (il == 8191) ? 1.0f : 0.0f;
    }
}

__global__ void k_final(float* __restrict__ out) {
    __shared__ double sred[8];
    int t = threadIdx.x;
    double h = 0.0;
    for (int k = t; k < NCODE; k += 256) {
        float p = (float)g_cnt[k] * (1.0f / 16384.0f);
        float arg = __fadd_rn(p, 1e-10f);
        h += (double)p * log((double)arg);
    }
    #pragma unroll
    for (int o = 16; o > 0; o >>= 1) h += __shfl_down_sync(0xffffffffu, h, o);
    int lane = t & 31, w = t >> 5;
    if (lane == 0) sred[w] = h;
    __syncthreads();
    if (w == 0) {
        double v = (lane < 8) ? sred[lane] : 0.0;
        #pragma unroll
        for (int o = 4; o > 0; o >>= 1) v += __shfl_down_sync(0xffffffffu, v, o);
        if (lane == 0) {
            out[OFF_PERP] = (float)exp(-v);
            float m = (float)(g_mse / (double)QELEMS);
            out[OFF_LOSS] = __fadd_rn(m, 0.25f * m);
        }
    }
}

// ---------------------------------------------------------------------------
extern "C" void kernel_launch(void* const* d_in, const int* in_sizes, int n_in,
                              void* d_out, int out_size) {
    const float* X = (const float*)d_in[0];   // [64,256,512] fp32
    const float* E = (const float*)d_in[1];   // [8192,512] fp32
    float* out = (float*)d_out;

    static int inited = 0;
    static cudaStream_t s1;
    static cudaEvent_t ev0, ev_conv, ev_sel, ev_enc;
    if (!inited) {
        cudaFuncSetAttribute(k_gemm_s8, cudaFuncAttributeMaxDynamicSharedMemorySize, GSMEM);
        cudaStreamCreateWithFlags(&s1, cudaStreamNonBlocking);
        cudaEventCreateWithFlags(&ev0, cudaEventDisableTiming);
        cudaEventCreateWithFlags(&ev_conv, cudaEventDisableTiming);
        cudaEventCreateWithFlags(&ev_sel, cudaEventDisableTiming);
        cudaEventCreateWithFlags(&ev_enc, cudaEventDisableTiming);
        inited = 1;
    }

    // Front: conv (s1) concurrent with init+norms (main); join before GEMM.
    cudaEventRecord(ev0, 0);
    cudaStreamWaitEvent(s1, ev0, 0);
    k_conv<<<12288, 256, 0, s1>>>(X, E);
    cudaEventRecord(ev_conv, s1);

    k_init<<<64, 256>>>();
    k_norms<<<3072, 256>>>(X, E);
    cudaStreamWaitEvent(0, ev_conv, 0);

    dim3 grid(NROW / 128, NCODE / 128);            // (128, 64), 2 CTAs/SM
    k_gemm_s8<<<grid, 256, GSMEM>>>();

    k_thresh<<<64, 256>>>();
    k_select<<<(NROW * 8) / 256, 256>>>(X, E);

    // Tail: encodings (s1) concurrent with quant_loss (main); join before final.
    cudaEventRecord(ev_sel, 0);
    cudaStreamWaitEvent(s1, ev_sel, 0);
    k_encodings<<<8192, 256, 0, s1>>>(out + OFF_ENC);
    cudaEventRecord(ev_enc, s1);

    k_quant_loss<<<QELEMS / 256, 256>>>(X, E, out + OFF_Q);
    cudaStreamWaitEvent(0, ev_enc, 0);
    k_final<<<1, 256>>>(out);
}

// round 15
// speedup vs baseline: 1.1095x; 1.0311x over previous
#include <cuda_runtime.h>
#include <math.h>

// Problem shape
#define NROW   16384     // 64*256 flattened input vectors
#define NCODE  8192      // codebook entries
#define DIM    512       // embedding dim
#define NTILE  64        // NCODE / 128
#define QELEMS (NROW * DIM)          // 8388608
#define OFF_LOSS 0
#define OFF_Q    1
#define OFF_PERP (1 + QELEMS)        // 8388609
#define OFF_ENC  (2 + QELEMS)        // 8388610

#define CAP      256                 // per-row candidate capacity (u64 list)
#define EPS_F    8e-4f
#define SX       24.0f
#define SE       1040384.0f          // 127 / (1/8192)
#define TWOINV   (2.0f / (SX * SE))

// Scratch (device globals; no allocations allowed)
__device__ int g_idx[NROW];
__device__ unsigned int g_cnt[NCODE];
__device__ float g_rowsq[NROW];       // A_m = fp32(sum x^2)
__device__ float g_csq[NCODE];        // B_k = fp32(sum e^2)
__device__ double g_mse;
__device__ unsigned g_amin[NROW];     // running approx min (float bits)
__device__ unsigned g_ccnt[NROW];     // candidate counts
__device__ unsigned g_tilemin[(size_t)NROW * NTILE];   // per (row, n-tile) min bits
__device__ float g_thr[NROW];         // final threshold
__device__ unsigned long long g_cand64[(size_t)NROW * CAP];  // (dist bits, code)
__device__ unsigned g_Xq[(size_t)NROW * DIM / 4];    // s8 packed
__device__ unsigned g_Eq[(size_t)NCODE * DIM / 4];   // s8 packed

// ---------------------------------------------------------------------------
__device__ __forceinline__ unsigned smem_u32(const void* p) {
    unsigned a;
    asm("{ .reg .u64 t; cvta.to.shared.u64 t, %1; cvt.u32.u64 %0, t; }" : "=r"(a) : "l"(p));
    return a;
}
__device__ __forceinline__ void cp_async16(unsigned dst, const void* src) {
    asm volatile("cp.async.cg.shared.global [%0], [%1], 16;" :: "r"(dst), "l"(src) : "memory");
}
__device__ __forceinline__ void cp_commit() {
    asm volatile("cp.async.commit_group;" ::: "memory");
}
__device__ __forceinline__ void cp_wait1() {
    asm volatile("cp.async.wait_group 1;" ::: "memory");
}
__device__ __forceinline__ void cp_wait0() {
    asm volatile("cp.async.wait_group 0;" ::: "memory");
}
__device__ __forceinline__ void ldsm_x4(unsigned& r0, unsigned& r1, unsigned& r2, unsigned& r3,
                                        unsigned addr) {
    asm volatile("ldmatrix.sync.aligned.m8n8.x4.shared.b16 {%0,%1,%2,%3}, [%4];"
                 : "=r"(r0), "=r"(r1), "=r"(r2), "=r"(r3) : "r"(addr));
}
__device__ __forceinline__ void mma16832s8(int* c, const unsigned* a, const unsigned* b) {
    asm volatile("mma.sync.aligned.m16n8k32.row.col.s32.s8.s8.s32 "
                 "{%0,%1,%2,%3}, {%4,%5,%6,%7}, {%8,%9}, {%0,%1,%2,%3};"
                 : "+r"(c[0]), "+r"(c[1]), "+r"(c[2]), "+r"(c[3])
                 : "r"(a[0]), "r"(a[1]), "r"(a[2]), "r"(a[3]), "r"(b[0]), "r"(b[1]));
}
__device__ __forceinline__ unsigned sw128(unsigned off) { return off ^ ((off >> 3) & 0x70u); }
__device__ __forceinline__ int q8(float v, float s) {
    int q = __float2int_rn(v * s);
    return q > 127 ? 127 : (q < -127 ? -127 : q);
}

// ---------------------------------------------------------------------------
// Fused int8 quantization of X and E (filter precision only).
__global__ void k_conv(const float* __restrict__ X, const float* __restrict__ E) {
    int i = blockIdx.x * blockDim.x + threadIdx.x;
    if (i < QELEMS / 4) {
        float4 v = ((const float4*)X)[i];
        g_Xq[i] = (unsigned)(q8(v.x, SX) & 255) | ((unsigned)(q8(v.y, SX) & 255) << 8) |
                  ((unsigned)(q8(v.z, SX) & 255) << 16) | ((unsigned)(q8(v.w, SX) & 255) << 24);
    } else {
        int j = i - QELEMS / 4;
        if (j >= (NCODE * DIM) / 4) return;
        float4 v = ((const float4*)E)[j];
        g_Eq[j] = (unsigned)(q8(v.x, SE) & 255) | ((unsigned)(q8(v.y, SE) & 255) << 8) |
                  ((unsigned)(q8(v.z, SE) & 255) << 16) | ((unsigned)(q8(v.w, SE) & 255) << 24);
    }
}

__global__ void k_init() {
    int i = blockIdx.x * blockDim.x + threadIdx.x;
    if (i < NROW) { g_amin[i] = 0x7F800000u; g_ccnt[i] = 0u; }
    if (i < NCODE) g_cnt[i] = 0u;
    if (i == 0) g_mse = 0.0;
}

// One warp per vector: squared L2 norms (double accum, rounded to fp32).
__global__ void k_norms(const float* __restrict__ X, const float* __restrict__ E) {
    int gwarp = (blockIdx.x * blockDim.x + threadIdx.x) >> 5;
    int lane = threadIdx.x & 31;
    const float* base; float* out; int nid;
    if (gwarp < NROW)      { base = X + (size_t)gwarp * DIM; out = g_rowsq; nid = gwarp; }
    else if (gwarp < NROW + NCODE) { nid = gwarp - NROW; base = E + (size_t)nid * DIM; out = g_csq; }
    else return;
    double s = 0.0;
    #pragma unroll 4
    for (int d = lane; d < DIM; d += 32) { float v = base[d]; s += (double)v * (double)v; }
    #pragma unroll
    for (int o = 16; o > 0; o >>= 1) s += __shfl_down_sync(0xffffffffu, s, o);
    if (lane == 0) out[nid] = (float)s;
}

// ---------------------------------------------------------------------------
// Bulk-async zero fill of the encodings region (bypasses the STG issue-rate
// wall: one cp.async.bulk per 16KB instead of 1024 STG.128). Co-runs with the
// GEMM using almost no SM issue/LSU resources. Body covers the 16B-aligned
// span [p+2, p+2+134217724 floats); the 4 edge floats are scalar-stored.
#define ZCHUNK 16384
#define ZBODY  536870896ull          // (NROW*NCODE - 4) * 4 bytes
#define ZNFULL (ZBODY / ZCHUNK)      // 32767 full chunks
#define ZREM   (ZBODY % ZCHUNK)      // 16368 (multiple of 16)

__global__ void k_zero_tma(float* __restrict__ p) {
    __shared__ __align__(16) char buf[ZCHUNK];
    for (int i = threadIdx.x; i < ZCHUNK / 4; i += blockDim.x)
        ((unsigned*)buf)[i] = 0u;
    __syncthreads();
    asm volatile("fence.proxy.async.shared::cta;" ::: "memory");
    if (threadIdx.x == 0) {
        unsigned sa = smem_u32(buf);
        char* base = (char*)(p + 2);
        for (size_t c = blockIdx.x; c < ZNFULL; c += gridDim.x) {
            asm volatile("cp.async.bulk.global.shared::cta.bulk_group [%0], [%1], %2;"
                         :: "l"(base + c * (size_t)ZCHUNK), "r"(sa), "r"((unsigned)ZCHUNK)
                         : "memory");
            asm volatile("cp.async.bulk.commit_group;" ::: "memory");
            asm volatile("cp.async.bulk.wait_group 32;" ::: "memory");
        }
        if (blockIdx.x == 0) {
            asm volatile("cp.async.bulk.global.shared::cta.bulk_group [%0], [%1], %2;"
                         :: "l"(base + ZNFULL * (size_t)ZCHUNK), "r"(sa), "r"((unsigned)ZREM)
                         : "memory");
            asm volatile("cp.async.bulk.commit_group;" ::: "memory");
            p[0] = 0.f; p[1] = 0.f;
            p[(size_t)NROW * NCODE - 2] = 0.f;
            p[(size_t)NROW * NCODE - 1] = 0.f;
        }
        asm volatile("cp.async.bulk.wait_group 0;" ::: "memory");
    }
}

__global__ void k_ones(float* __restrict__ enc) {
    int i = blockIdx.x * blockDim.x + threadIdx.x;
    if (i < NROW) enc[(size_t)i * NCODE + g_idx[i]] = 1.0f;
}

// ---------------------------------------------------------------------------
// Phase 1: int8 mma.sync GEMM filter, 2 CTAs/SM (measured 256us, tensor 49%).
#define NKIT   4                     // 512 / 128
#define A_ST   (128 * 128)           // 16384
#define B_ST   (128 * 128)           // 16384
#define STG_BY (A_ST + B_ST)         // 32768
#define NSTG   3
#define OFF_RM (NSTG * STG_BY)       // 98304 rowmin[128] u32
#define OFF_TH (OFF_RM + 512)        // thr[128] f32
#define OFF_CS (OFF_TH + 512)        // csq_s[128] f32
#define OFF_RS (OFF_CS + 512)        // rowsq_s[128] f32
#define GSMEM  (OFF_RS + 512)        // 100352 -> 2 CTAs/SM

__global__ __launch_bounds__(256, 2)
void k_gemm_s8() {
    extern __shared__ char sm[];
    const int tid = threadIdx.x;
    const int wid = tid >> 5, lane = tid & 31;
    const int warp_m = wid & 3, warp_n = wid >> 2;     // 4x2 warps
    const int grp = lane >> 2, tid4 = lane & 3;
    const int bm = blockIdx.x * 128, bn = blockIdx.y * 128;   // x = row tile
    const unsigned base = smem_u32(sm);

    unsigned* rowmin = (unsigned*)(sm + OFF_RM);
    float* thr_s   = (float*)(sm + OFF_TH);
    float* csq_s   = (float*)(sm + OFF_CS);
    float* rowsq_s = (float*)(sm + OFF_RS);

    if (tid < 128) {
        rowmin[tid] = 0xFFFFFFFFu;
        rowsq_s[tid] = g_rowsq[bm + tid];
        csq_s[tid] = g_csq[bn + tid];
    }

    const char* XA = (const char*)g_Xq + (size_t)bm * DIM;
    const char* EB = (const char*)g_Eq + (size_t)bn * DIM;

    int acc[2][8][4];
    #pragma unroll
    for (int mi = 0; mi < 2; mi++)
        #pragma unroll
        for (int ni = 0; ni < 8; ni++)
            #pragma unroll
            for (int c = 0; c < 4; c++) acc[mi][ni][c] = 0;

    auto issue = [&](int stage, int kt) {
        const int k0 = kt * 128;                      // byte offset in row
        const unsigned sA = base + stage * STG_BY;
        const unsigned sB = sA + A_ST;
        #pragma unroll
        for (int i = 0; i < 4; i++) {                 // A: 1024 chunks of 16B
            int u = tid + (i << 8);
            int r = u >> 3, q = u & 7;
            cp_async16(sA + sw128(r * 128 + q * 16), XA + (size_t)r * DIM + k0 + q * 16);
        }
        #pragma unroll
        for (int i = 0; i < 4; i++) {                 // B: 1024 chunks
            int u = tid + (i << 8);
            int r = u >> 3, q = u & 7;
            cp_async16(sB + sw128(r * 128 + q * 16), EB + (size_t)r * DIM + k0 + q * 16);
        }
        cp_commit();
    };

    issue(0, 0); issue(1, 1);

    const int a_row = warp_m * 32 + (lane & 15);          // + mi*16
    const int a_kb  = (lane >> 4) * 16;
    const int b_row = warp_n * 64 + (lane & 7) + ((lane >> 4) << 3);   // + nj*16
    const int b_kb  = ((lane >> 3) & 1) * 16;

    for (int kt = 0; kt < NKIT; kt++) {
        if (kt == NKIT - 1) cp_wait0(); else cp_wait1();
        __syncthreads();
        if (kt + 2 < NKIT) issue((kt + 2) % NSTG, kt + 2);

        const unsigned sA = base + (kt % NSTG) * STG_BY;
        const unsigned sB = sA + A_ST;

        #pragma unroll
        for (int ks = 0; ks < 4; ks++) {              // 4 x k32 per 128B row
            const int kb = ks * 32;
            unsigned a[2][4], b[8][2];
            #pragma unroll
            for (int mi = 0; mi < 2; mi++)
                ldsm_x4(a[mi][0], a[mi][1], a[mi][2], a[mi][3],
                        sA + sw128((a_row + mi * 16) * 128 + kb + a_kb));
            #pragma unroll
            for (int nj = 0; nj < 4; nj++) {
                unsigned r0, r1, r2, r3;
                ldsm_x4(r0, r1, r2, r3,
                        sB + sw128((b_row + nj * 16) * 128 + kb + b_kb));
                b[nj * 2][0] = r0;     b[nj * 2][1] = r1;
                b[nj * 2 + 1][0] = r2; b[nj * 2 + 1][1] = r3;
            }
            #pragma unroll
            for (int mi = 0; mi < 2; mi++)
                #pragma unroll
                for (int ni = 0; ni < 8; ni++)
                    mma16832s8(acc[mi][ni], a[mi], b[ni]);
        }
        __syncthreads();
    }

    // --- epilogue pass 1: per-row local min of approx dist ---
    #pragma unroll
    for (int mi = 0; mi < 2; mi++) {
        const int r0 = warp_m * 32 + mi * 16 + grp;
        const float A0 = rowsq_s[r0], A1 = rowsq_s[r0 + 8];
        float m0 = 3.4e38f, m1 = 3.4e38f;
        #pragma unroll
        for (int ni = 0; ni < 8; ni++) {
            const int n = warp_n * 64 + ni * 8 + tid4 * 2;
            const float B0 = csq_s[n], B1 = csq_s[n + 1];
            const int* cc = acc[mi][ni];
            m0 = fminf(m0, fminf(A0 + B0 - TWOINV * (float)cc[0],
                                 A0 + B1 - TWOINV * (float)cc[1]));
            m1 = fminf(m1, fminf(A1 + B0 - TWOINV * (float)cc[2],
                                 A1 + B1 - TWOINV * (float)cc[3]));
        }
        atomicMin(&rowmin[r0], __float_as_uint(m0));       // dists > 0
        atomicMin(&rowmin[r0 + 8], __float_as_uint(m1));
    }
    __syncthreads();
    if (tid < 128) {
        unsigned mine = rowmin[tid];
        g_tilemin[(size_t)(bm + tid) * NTILE + blockIdx.y] = mine;   // per-tile min
        unsigned old = atomicMin(&g_amin[bm + tid], mine);
        thr_s[tid] = __uint_as_float(old < mine ? old : mine) + EPS_F;
    }
    __syncthreads();

    // --- epilogue pass 2: append (dist,code) within EPS of running min ---
    #pragma unroll
    for (int mi = 0; mi < 2; mi++) {
        const int r0 = warp_m * 32 + mi * 16 + grp;
        const float A0 = rowsq_s[r0], A1 = rowsq_s[r0 + 8];
        const float t0 = thr_s[r0], t1 = thr_s[r0 + 8];
        #pragma unroll
        for (int ni = 0; ni < 8; ni++) {
            const int n = warp_n * 64 + ni * 8 + tid4 * 2;
            const float B0 = csq_s[n], B1 = csq_s[n + 1];
            const int* cc = acc[mi][ni];
            float d00 = A0 + B0 - TWOINV * (float)cc[0];
            float d01 = A0 + B1 - TWOINV * (float)cc[1];
            float d10 = A1 + B0 - TWOINV * (float)cc[2];
            float d11 = A1 + B1 - TWOINV * (float)cc[3];
            if (d00 < t0) { unsigned p = atomicAdd(&g_ccnt[bm + r0], 1u);
                if (p < CAP) g_cand64[(size_t)(bm + r0) * CAP + p] =
                    ((unsigned long long)__float_as_uint(d00) << 32) | (unsigned)(bn + n); }
            if (d01 < t0) { unsigned p = atomicAdd(&g_ccnt[bm + r0], 1u);
                if (p < CAP) g_cand64[(size_t)(bm + r0) * CAP + p] =
                    ((unsigned long long)__float_as_uint(d01) << 32) | (unsigned)(bn + n + 1); }
            if (d10 < t1) { unsigned p = atomicAdd(&g_ccnt[bm + r0 + 8], 1u);
                if (p < CAP) g_cand64[(size_t)(bm + r0 + 8) * CAP + p] =
                    ((unsigned long long)__float_as_uint(d10) << 32) | (unsigned)(bn + n); }
            if (d11 < t1) { unsigned p = atomicAdd(&g_ccnt[bm + r0 + 8], 1u);
                if (p < CAP) g_cand64[(size_t)(bm + r0 + 8) * CAP + p] =
                    ((unsigned long long)__float_as_uint(d11) << 32) | (unsigned)(bn + n + 1); }
        }
    }
}

// ---------------------------------------------------------------------------
// Final per-row threshold from tile minima: thr = min over 64 tiles + EPS.
__global__ void k_thresh() {
    int r = blockIdx.x * blockDim.x + threadIdx.x;
    if (r >= NROW) return;
    unsigned m = 0xFFFFFFFFu;
    #pragma unroll 8
    for (int t = 0; t < NTILE; t++) {
        unsigned v = g_tilemin[(size_t)r * NTILE + t];
        if (v < m) m = v;
    }
    g_thr[r] = __uint_as_float(m) + EPS_F;
}

// ---------------------------------------------------------------------------
// Phase 2: filter stored candidates by the FINAL threshold, then exact
// re-verification bit-identical to R1's fp32 path.
__global__ void k_select(const float* __restrict__ X, const float* __restrict__ E) {
    int gid = blockIdx.x * blockDim.x + threadIdx.x;
    int r = gid >> 3, slot = gid & 7;
    if (r >= NROW) return;
    unsigned cnt = g_ccnt[r];
    const float thr = g_thr[r];
    const float* x = X + (size_t)r * DIM;
    const float A = g_rowsq[r];
    unsigned long long best = 0xFFFFFFFFFFFFFFFFULL;
    if (cnt <= CAP) {
        for (unsigned i = slot; i < cnt; i += 8) {
            unsigned long long kc = g_cand64[(size_t)r * CAP + i];
            if (__uint_as_float((unsigned)(kc >> 32)) >= thr) continue;
            int c = (int)(kc & 0xFFFFu);
            const float* e = E + (size_t)c * DIM;
            float acc = 0.0f;
            #pragma unroll 8
            for (int k = 0; k < DIM; k++) acc = fmaf(x[k], e[k], acc);
            float dist = __fsub_rn(__fadd_rn(A, g_csq[c]), 2.0f * acc);
            unsigned long long key =
                ((unsigned long long)__float_as_uint(dist) << 32) | (unsigned)c;
            if (key < best) best = key;
        }
    } else {
        // overflow fallback (expected ~never): scan tiles whose min < thr
        for (int t = 0; t < NTILE; t++) {
            if (__uint_as_float(g_tilemin[(size_t)r * NTILE + t]) >= thr) continue;
            for (int c = t * 128 + slot; c < (t + 1) * 128; c += 8) {
                const float* e = E + (size_t)c * DIM;
                float acc = 0.0f;
                #pragma unroll 8
                for (int k = 0; k < DIM; k++) acc = fmaf(x[k], e[k], acc);
                float dist = __fsub_rn(__fadd_rn(A, g_csq[c]), 2.0f * acc);
                unsigned long long key =
                    ((unsigned long long)__float_as_uint(dist) << 32) | (unsigned)c;
                if (key < best) best = key;
            }
        }
    }
    #pragma unroll
    for (int o = 4; o > 0; o >>= 1) {
        unsigned long long t = __shfl_down_sync(0xffffffffu, best, o, 8);
        if (t < best) best = t;
    }
    if (slot == 0) {
        int idx = (int)(unsigned)(best & 0xFFFFFFFFu);
        g_idx[r] = idx;
        atomicAdd(&g_cnt[idx], 1u);
    }
}

// ---------------------------------------------------------------------------
__global__ void k_quant_loss(const float* __restrict__ X, const float* __restrict__ E,
                             float* __restrict__ q_out) {
    __shared__ double sred[8];
    int i = blockIdx.x * blockDim.x + threadIdx.x;
    int row = i >> 9;
    int d = i & 511;
    int idx = g_idx[row];
    float q = E[(size_t)idx * DIM + d];
    float x = X[i];
    float diff = __fsub_rn(q, x);
    q_out[i] = __fadd_rn(x, diff);
    double local = (double)diff * (double)diff;
    #pragma unroll
    for (int o = 16; o > 0; o >>= 1) local += __shfl_down_sync(0xffffffffu, local, o);
    int lane = threadIdx.x & 31, w = threadIdx.x >> 5;
    if (lane == 0) sred[w] = local;
    __syncthreads();
    if (w == 0) {
        double v = (lane < 8) ? sred[lane] : 0.0;
        #pragma unroll
        for (int o = 4; o > 0; o >>= 1) v += __shfl_down_sync(0xffffffffu, v, o);
        if (lane == 0) atomicAdd(&g_mse, v);
    }
}

__global__ void k_final(float* __restrict__ out) {
    __shared__ double sred[8];
    int t = threadIdx.x;
    double h = 0.0;
    for (int k = t; k < NCODE; k += 256) {
        float p = (float)g_cnt[k] * (1.0f / 16384.0f);
        float arg = __fadd_rn(p, 1e-10f);
        h += (double)p * log((double)arg);
    }
    #pragma unroll
    for (int o = 16; o > 0; o >>= 1) h += __shfl_down_sync(0xffffffffu, h, o);
    int lane = t & 31, w = t >> 5;
    if (lane == 0) sred[w] = h;
    __syncthreads();
    if (w == 0) {
        double v = (lane < 8) ? sred[lane] : 0.0;
        #pragma unroll
        for (int o = 4; o > 0; o >>= 1) v += __shfl_down_sync(0xffffffffu, v, o);
        if (lane == 0) {
            out[OFF_PERP] = (float)exp(-v);
            float m = (float)(g_mse / (double)QELEMS);
            out[OFF_LOSS] = __fadd_rn(m, 0.25f * m);
        }
    }
}

// ---------------------------------------------------------------------------
extern "C" void kernel_launch(void* const* d_in, const int* in_sizes, int n_in,
                              void* d_out, int out_size) {
    const float* X = (const float*)d_in[0];   // [64,256,512] fp32
    const float* E = (const float*)d_in[1];   // [8192,512] fp32
    float* out = (float*)d_out;

    static int inited = 0;
    static cudaStream_t s1;
    static cudaEvent_t ev0, ev_zero;
    if (!inited) {
        cudaFuncSetAttribute(k_gemm_s8, cudaFuncAttributeMaxDynamicSharedMemorySize, GSMEM);
        cudaStreamCreateWithFlags(&s1, cudaStreamNonBlocking);
        cudaEventCreateWithFlags(&ev0, cudaEventDisableTiming);
        cudaEventCreateWithFlags(&ev_zero, cudaEventDisableTiming);
        inited = 1;
    }

    // Fork at t=0: bulk-async zero fill of the encodings region on s1.
    // Nearly zero SM resource usage -> genuinely co-runs with the GEMM.
    cudaEventRecord(ev0, 0);
    cudaStreamWaitEvent(s1, ev0, 0);
    k_zero_tma<<<148, 128, 0, s1>>>(out + OFF_ENC);
    cudaEventRecord(ev_zero, s1);

    k_conv<<<12288, 256>>>(X, E);
    k_init<<<64, 256>>>();
    k_norms<<<3072, 256>>>(X, E);

    dim3 grid(NROW / 128, NCODE / 128);            // (128, 64), 2 CTAs/SM
    k_gemm_s8<<<grid, 256, GSMEM>>>();

    k_thresh<<<64, 256>>>();
    k_select<<<(NROW * 8) / 256, 256>>>(X, E);

    // Ones need both select results and the zero fill.
    cudaStreamWaitEvent(0, ev_zero, 0);
    k_ones<<<64, 256>>>(out + OFF_ENC);
    k_quant_loss<<<QELEMS / 256, 256>>>(X, E, out + OFF_Q);
    k_final<<<1, 256>>>(out);
}